// round 1
// baseline (speedup 1.0000x reference)
#include <cuda_runtime.h>
#include <math.h>

// ---------------- problem constants ----------------
#define BB   2
#define SSQ  2048
#define DDIM 1024
#define NH   16
#define HD   64
#define FFN  4096
#define MR   (BB*SSQ)          // 4096 rows in flattened [B*S, D]

// ---------------- scratch (device globals; no allocation) ----------------
__device__ float g_q [(size_t)BB*SSQ*DDIM];
__device__ float g_k [(size_t)BB*SSQ*DDIM];
__device__ float g_v [(size_t)BB*SSQ*DDIM];
__device__ float g_s [(size_t)BB*NH*SSQ*SSQ];   // scores / probs (537 MB)
__device__ float g_o [(size_t)BB*SSQ*DDIM];
__device__ float g_x1[(size_t)BB*SSQ*DDIM];
__device__ float g_ln[(size_t)BB*SSQ*DDIM];
__device__ float g_h [(size_t)BB*SSQ*FFN];
__device__ float g_x2[(size_t)BB*SSQ*DDIM];

// ---------------------------------------------------------------
// Generic NT GEMM: C[m,n] = alpha * sum_k A[m,k]*B[n,k]  (+ epilogue)
// Tiles 64x64, BK=16, 256 threads, 4x4 microtile. All dims multiples of 64/16.
// EPI: 0 = none
//      1 = + addM[m,n]                       (scores bias / o-proj residual)
//      2 = + biasN[n], then exact GELU       (ffn1)
//      3 = + addM[m,n] + biasN[n]            (ffn2 residual + bias)
// ---------------------------------------------------------------
template<int EPI>
__global__ __launch_bounds__(256)
void gemm_nt(const float* __restrict__ A, const float* __restrict__ B,
             float* __restrict__ C,
             int M, int N, int K, int lda, int ldb, int ldc,
             long long sA, long long sB, long long sC,
             float alpha,
             const float* __restrict__ addM, int ldadd, long long sAdd,
             const float* __restrict__ biasN)
{
    A += (long long)blockIdx.z * sA;
    B += (long long)blockIdx.z * sB;
    C += (long long)blockIdx.z * sC;
    if (EPI == 1 || EPI == 3) addM += (long long)blockIdx.z * sAdd;

    __shared__ float As[16][68];
    __shared__ float Bs[16][68];

    const int tid = threadIdx.x;
    const int tx = tid & 15, ty = tid >> 4;
    const int m0 = blockIdx.y * 64, n0 = blockIdx.x * 64;
    const int lr = tid >> 2;            // 0..63
    const int lk = (tid & 3) * 4;       // 0,4,8,12

    float acc[4][4] = {};

    for (int k0 = 0; k0 < K; k0 += 16) {
        float4 av = *(const float4*)&A[(size_t)(m0 + lr) * lda + k0 + lk];
        float4 bv = *(const float4*)&B[(size_t)(n0 + lr) * ldb + k0 + lk];
        As[lk+0][lr] = av.x; As[lk+1][lr] = av.y; As[lk+2][lr] = av.z; As[lk+3][lr] = av.w;
        Bs[lk+0][lr] = bv.x; Bs[lk+1][lr] = bv.y; Bs[lk+2][lr] = bv.z; Bs[lk+3][lr] = bv.w;
        __syncthreads();
        #pragma unroll
        for (int k = 0; k < 16; k++) {
            float4 a = *(const float4*)&As[k][ty*4];
            float4 b = *(const float4*)&Bs[k][tx*4];
            float ar[4] = {a.x, a.y, a.z, a.w};
            float br[4] = {b.x, b.y, b.z, b.w};
            #pragma unroll
            for (int i = 0; i < 4; i++)
                #pragma unroll
                for (int j = 0; j < 4; j++)
                    acc[i][j] += ar[i] * br[j];
        }
        __syncthreads();
    }

    #pragma unroll
    for (int i = 0; i < 4; i++) {
        int row = m0 + ty*4 + i;
        #pragma unroll
        for (int j = 0; j < 4; j++) {
            int col = n0 + tx*4 + j;
            float v = acc[i][j] * alpha;
            if (EPI == 1) v += addM[(size_t)row * ldadd + col];
            if (EPI == 2) { v += biasN[col]; v = 0.5f * v * (1.0f + erff(v * 0.70710678118654752f)); }
            if (EPI == 3) v += addM[(size_t)row * ldadd + col] + biasN[col];
            C[(size_t)row * ldc + col] = v;
        }
    }
}

// ---------------------------------------------------------------
// NN GEMM for PV: C[m,n] = sum_k A[m,k]*B[k,n]   (N=64 per head)
// ---------------------------------------------------------------
__global__ __launch_bounds__(256)
void gemm_nn(const float* __restrict__ A, const float* __restrict__ B,
             float* __restrict__ C,
             int M, int N, int K, int lda, int ldb, int ldc,
             long long sA, long long sB, long long sC)
{
    A += (long long)blockIdx.z * sA;
    B += (long long)blockIdx.z * sB;
    C += (long long)blockIdx.z * sC;

    __shared__ float As[16][68];
    __shared__ float Bs[16][68];

    const int tid = threadIdx.x;
    const int tx = tid & 15, ty = tid >> 4;
    const int m0 = blockIdx.y * 64, n0 = blockIdx.x * 64;
    const int lr = tid >> 2;
    const int lk = (tid & 3) * 4;
    const int bk = tid >> 4;            // 0..15
    const int bn = (tid & 15) * 4;      // 0..60

    float acc[4][4] = {};

    for (int k0 = 0; k0 < K; k0 += 16) {
        float4 av = *(const float4*)&A[(size_t)(m0 + lr) * lda + k0 + lk];
        float4 bv = *(const float4*)&B[(size_t)(k0 + bk) * ldb + n0 + bn];
        As[lk+0][lr] = av.x; As[lk+1][lr] = av.y; As[lk+2][lr] = av.z; As[lk+3][lr] = av.w;
        Bs[bk][bn+0] = bv.x; Bs[bk][bn+1] = bv.y; Bs[bk][bn+2] = bv.z; Bs[bk][bn+3] = bv.w;
        __syncthreads();
        #pragma unroll
        for (int k = 0; k < 16; k++) {
            float4 a = *(const float4*)&As[k][ty*4];
            float4 b = *(const float4*)&Bs[k][tx*4];
            float ar[4] = {a.x, a.y, a.z, a.w};
            float br[4] = {b.x, b.y, b.z, b.w};
            #pragma unroll
            for (int i = 0; i < 4; i++)
                #pragma unroll
                for (int j = 0; j < 4; j++)
                    acc[i][j] += ar[i] * br[j];
        }
        __syncthreads();
    }

    #pragma unroll
    for (int i = 0; i < 4; i++) {
        int row = m0 + ty*4 + i;
        #pragma unroll
        for (int j = 0; j < 4; j++)
            C[(size_t)row * ldc + n0 + tx*4 + j] = acc[i][j];
    }
}

// ---------------------------------------------------------------
// Row softmax over 2048 elements, in place. One block (256 thr) per row.
// ---------------------------------------------------------------
__global__ __launch_bounds__(256)
void softmax_rows(float* __restrict__ s)
{
    float* p = s + (size_t)blockIdx.x * SSQ;
    const int tid = threadIdx.x, lane = tid & 31, warp = tid >> 5;
    __shared__ float red[8];

    float v[8];
    float mx = -3.0e38f;
    #pragma unroll
    for (int i = 0; i < 8; i++) { v[i] = p[tid + i*256]; mx = fmaxf(mx, v[i]); }
    #pragma unroll
    for (int o = 16; o; o >>= 1) mx = fmaxf(mx, __shfl_xor_sync(0xffffffffu, mx, o));
    if (!lane) red[warp] = mx;
    __syncthreads();
    mx = red[0];
    #pragma unroll
    for (int i = 1; i < 8; i++) mx = fmaxf(mx, red[i]);

    float sum = 0.0f;
    #pragma unroll
    for (int i = 0; i < 8; i++) { v[i] = expf(v[i] - mx); sum += v[i]; }
    #pragma unroll
    for (int o = 16; o; o >>= 1) sum += __shfl_xor_sync(0xffffffffu, sum, o);
    __syncthreads();
    if (!lane) red[warp] = sum;
    __syncthreads();
    sum = 0.0f;
    #pragma unroll
    for (int i = 0; i < 8; i++) sum += red[i];

    float inv = 1.0f / sum;
    #pragma unroll
    for (int i = 0; i < 8; i++) p[tid + i*256] = v[i] * inv;
}

// ---------------------------------------------------------------
// LayerNorm over rows of 1024. One block (256 thr) per row.
// ---------------------------------------------------------------
__global__ __launch_bounds__(256)
void layernorm_rows(const float* __restrict__ x, float* __restrict__ y,
                    const float* __restrict__ gg, const float* __restrict__ bb)
{
    const float* p = x + (size_t)blockIdx.x * DDIM;
    float* q = y + (size_t)blockIdx.x * DDIM;
    const int tid = threadIdx.x, lane = tid & 31, warp = tid >> 5;
    __shared__ float r1[8], r2[8];

    float v[4];
    float s = 0.0f, s2 = 0.0f;
    #pragma unroll
    for (int i = 0; i < 4; i++) { v[i] = p[tid + i*256]; s += v[i]; s2 += v[i]*v[i]; }
    #pragma unroll
    for (int o = 16; o; o >>= 1) {
        s  += __shfl_xor_sync(0xffffffffu, s,  o);
        s2 += __shfl_xor_sync(0xffffffffu, s2, o);
    }
    if (!lane) { r1[warp] = s; r2[warp] = s2; }
    __syncthreads();
    s = 0.0f; s2 = 0.0f;
    #pragma unroll
    for (int i = 0; i < 8; i++) { s += r1[i]; s2 += r2[i]; }

    float mean = s * (1.0f / DDIM);
    float var  = s2 * (1.0f / DDIM) - mean * mean;
    float inv  = rsqrtf(var + 1e-5f);
    #pragma unroll
    for (int i = 0; i < 4; i++) {
        int c = tid + i*256;
        q[c] = (v[i] - mean) * inv * gg[c] + bb[c];
    }
}

// ---------------------------------------------------------------
extern "C" void kernel_launch(void* const* d_in, const int* in_sizes, int n_in,
                              void* d_out, int out_size)
{
    const float* x_q  = (const float*)d_in[0];
    const float* x_kv = (const float*)d_in[1];
    const float* bias = (const float*)d_in[2];
    const float* Wq   = (const float*)d_in[3];
    const float* Wk   = (const float*)d_in[4];
    const float* Wv   = (const float*)d_in[5];
    const float* Wo   = (const float*)d_in[6];
    const float* W1   = (const float*)d_in[7];
    const float* b1   = (const float*)d_in[8];
    const float* W2   = (const float*)d_in[9];
    const float* b2   = (const float*)d_in[10];
    const float* g1   = (const float*)d_in[11];
    const float* be1  = (const float*)d_in[12];
    const float* g2   = (const float*)d_in[13];
    const float* be2  = (const float*)d_in[14];
    float* out = (float*)d_out;

    float *pq, *pk, *pv, *ps, *po, *px1, *pln, *ph, *px2;
    cudaGetSymbolAddress((void**)&pq,  g_q);
    cudaGetSymbolAddress((void**)&pk,  g_k);
    cudaGetSymbolAddress((void**)&pv,  g_v);
    cudaGetSymbolAddress((void**)&ps,  g_s);
    cudaGetSymbolAddress((void**)&po,  g_o);
    cudaGetSymbolAddress((void**)&px1, g_x1);
    cudaGetSymbolAddress((void**)&pln, g_ln);
    cudaGetSymbolAddress((void**)&ph,  g_h);
    cudaGetSymbolAddress((void**)&px2, g_x2);

    const long long SD  = (long long)SSQ * DDIM;     // per-batch stride in [B,S,D]
    const long long SS2 = (long long)SSQ * SSQ;      // per-head stride in [B,H,S,S]

    // 1) Q/K/V projections: [4096,1024] = [4096,1024] @ W^T
    {
        dim3 gr(DDIM/64, MR/64, 1);
        gemm_nt<0><<<gr, 256>>>(x_q,  Wq, pq, MR, DDIM, DDIM, DDIM, DDIM, DDIM,
                                0, 0, 0, 1.0f, nullptr, 0, 0, nullptr);
        gemm_nt<0><<<gr, 256>>>(x_kv, Wk, pk, MR, DDIM, DDIM, DDIM, DDIM, DDIM,
                                0, 0, 0, 1.0f, nullptr, 0, 0, nullptr);
        gemm_nt<0><<<gr, 256>>>(x_kv, Wv, pv, MR, DDIM, DDIM, DDIM, DDIM, DDIM,
                                0, 0, 0, 1.0f, nullptr, 0, 0, nullptr);
    }

    // 2) scores[b,h] = Q_h @ K_h^T / 8 + bias[b,h]   (per-head views into [B,S,D])
    for (int b = 0; b < BB; b++) {
        dim3 gr(SSQ/64, SSQ/64, NH);
        gemm_nt<1><<<gr, 256>>>(pq + (long long)b*SD, pk + (long long)b*SD,
                                ps + (long long)b*NH*SS2,
                                SSQ, SSQ, HD, DDIM, DDIM, SSQ,
                                HD, HD, SS2,
                                0.125f,
                                bias + (long long)b*NH*SS2, SSQ, SS2,
                                nullptr);
    }

    // 3) softmax rows
    softmax_rows<<<BB*NH*SSQ, 256>>>(ps);

    // 4) O_h = P @ V_h  (NN, N=64 per head)
    for (int b = 0; b < BB; b++) {
        dim3 gr(1, SSQ/64, NH);
        gemm_nn<<<gr, 256>>>(ps + (long long)b*NH*SS2, pv + (long long)b*SD,
                             po + (long long)b*SD,
                             SSQ, HD, SSQ, SSQ, DDIM, DDIM,
                             SS2, HD, HD);
    }

    // 5) x1 = x_q + O @ Wo^T
    gemm_nt<1><<<dim3(DDIM/64, MR/64, 1), 256>>>(po, Wo, px1,
                                                 MR, DDIM, DDIM, DDIM, DDIM, DDIM,
                                                 0, 0, 0, 1.0f, x_q, DDIM, 0, nullptr);

    // 6) ln1 = LayerNorm(x1)
    layernorm_rows<<<MR, 256>>>(px1, pln, g1, be1);

    // 7) h = gelu(ln1 @ W1^T + b1)
    gemm_nt<2><<<dim3(FFN/64, MR/64, 1), 256>>>(pln, W1, ph,
                                                MR, FFN, DDIM, DDIM, DDIM, FFN,
                                                0, 0, 0, 1.0f, nullptr, 0, 0, b1);

    // 8) x2 = x1 + h @ W2^T + b2
    gemm_nt<3><<<dim3(DDIM/64, MR/64, 1), 256>>>(ph, W2, px2,
                                                 MR, DDIM, FFN, FFN, FFN, DDIM,
                                                 0, 0, 0, 1.0f, px1, DDIM, 0, b2);

    // 9) out = LayerNorm(x2)
    layernorm_rows<<<MR, 256>>>(px2, out, g2, be2);
}

// round 4
// speedup vs baseline: 2.0487x; 2.0487x over previous
#include <cuda_runtime.h>
#include <cuda_bf16.h>
#include <cstdint>
#include <math.h>

typedef __nv_bfloat16 bf16;
typedef unsigned int u32;

#define BB 2
#define SQ 2048
#define DM 1024
#define NHD 16
#define FF 4096
#define MR (BB*SQ)

// ------------------- scratch (device globals) -------------------
__device__ bf16 s_xq_h[MR*DM], s_xq_l[MR*DM];
__device__ bf16 s_xk_h[MR*DM], s_xk_l[MR*DM];
__device__ bf16 s_wq_h[DM*DM], s_wq_l[DM*DM];
__device__ bf16 s_wk_h[DM*DM], s_wk_l[DM*DM];
__device__ bf16 s_wv_h[DM*DM], s_wv_l[DM*DM];
__device__ bf16 s_wo_h[DM*DM], s_wo_l[DM*DM];
__device__ bf16 s_w1_h[FF*DM], s_w1_l[FF*DM];
__device__ bf16 s_w2_h[DM*FF], s_w2_l[DM*FF];
__device__ bf16 s_q_h[MR*DM],  s_q_l[MR*DM];
__device__ bf16 s_k_h[MR*DM],  s_k_l[MR*DM];
__device__ float s_v[MR*DM];
__device__ bf16 s_vt_h[(size_t)BB*DM*SQ], s_vt_l[(size_t)BB*DM*SQ];
__device__ float s_sc[(size_t)BB*NHD*SQ*SQ];
__device__ bf16 s_p_h[(size_t)BB*NHD*SQ*SQ], s_p_l[(size_t)BB*NHD*SQ*SQ];
__device__ bf16 s_o_h[MR*DM],  s_o_l[MR*DM];
__device__ float s_x1[MR*DM];
__device__ bf16 s_ln_h[MR*DM], s_ln_l[MR*DM];
__device__ bf16 s_hh[(size_t)MR*FF], s_hl[(size_t)MR*FF];
__device__ float s_x2[MR*DM];

// ------------------- helpers -------------------
__device__ __forceinline__ u32 smem_u32(const void* p) {
    return (u32)__cvta_generic_to_shared(p);
}
#define CP16(dst, src) \
    asm volatile("cp.async.cg.shared.global [%0], [%1], 16;" :: "r"(dst), "l"(src))
#define CP_COMMIT() asm volatile("cp.async.commit_group;" ::: "memory")
#define CP_WAIT1()  asm volatile("cp.async.wait_group 1;" ::: "memory")
#define CP_WAIT0()  asm volatile("cp.async.wait_group 0;" ::: "memory")

#define LDSM4(r0, r1, r2, r3, addr) \
    asm volatile("ldmatrix.sync.aligned.m8n8.x4.shared.b16 {%0,%1,%2,%3}, [%4];" \
        : "=r"(r0), "=r"(r1), "=r"(r2), "=r"(r3) : "r"(addr))

__device__ __forceinline__ void mma_bf16(float* c, const u32* a, const u32* b) {
    asm volatile("mma.sync.aligned.m16n8k16.row.col.f32.bf16.bf16.f32 "
        "{%0,%1,%2,%3}, {%4,%5,%6,%7}, {%8,%9}, {%0,%1,%2,%3};"
        : "+f"(c[0]), "+f"(c[1]), "+f"(c[2]), "+f"(c[3])
        : "r"(a[0]), "r"(a[1]), "r"(a[2]), "r"(a[3]), "r"(b[0]), "r"(b[1]));
}

__device__ __forceinline__ void split2(float v, bf16& h, bf16& l) {
    h = __float2bfloat16(v);
    l = __float2bfloat16(v - __bfloat162float(h));
}

// ------------------- HMMA GEMM -------------------
// C[m,n] = alpha * sum_k A[m,k]*B[n,k] (+ epilogue); A/B bf16 hi/lo splits (K-major).
// EPI: 0 none; 1 +addM; 2 +biasN then GELU; 3 +addM +biasN
// OUTM: 0 -> fp32 C; 1 -> split bf16 (Ch, Cl)
// BM=128 fixed. BN in {128, 64}. BK=32. 256 threads, warps 2(M)x4(N).
template<int EPI, int OUTM, int BN>
__global__ __launch_bounds__(256, 1)
void gemm_mma(const bf16* __restrict__ Ah, const bf16* __restrict__ Al,
              const bf16* __restrict__ Bh, const bf16* __restrict__ Bl,
              float* __restrict__ C, bf16* __restrict__ Ch, bf16* __restrict__ Cl,
              int K, int lda, int ldb, int ldc,
              long long sA, long long sB, long long sC,
              float alpha,
              const float* __restrict__ addM, int ldadd, long long sAdd,
              const float* __restrict__ biasN)
{
    constexpr int WN  = BN / 4;        // warp n-extent
    constexpr int NT  = WN / 8;        // n8 tiles per warp (4 or 2)
    constexpr u32 ROWB  = 80;          // padded row stride bytes (64 data + 16)
    constexpr u32 A_LO  = 128 * ROWB;  // 10240
    constexpr u32 B_OFF = 2 * 128 * ROWB;
    constexpr u32 B_LO  = (u32)BN * ROWB;
    constexpr u32 STG   = (2 * 128 + 2 * BN) * ROWB;

    extern __shared__ char smem[];
    const u32 sbase = smem_u32(smem);
    const int tid = threadIdx.x, lane = tid & 31, wid = tid >> 5;
    const int wm = wid & 1, wn = wid >> 1;
    const long long z = blockIdx.z;

    Ah += z * sA;  Al += z * sA;
    Bh += z * sB;  Bl += z * sB;

    const int m0 = blockIdx.y * 128, n0 = blockIdx.x * BN;

    float acc[4][NT][4];
    #pragma unroll
    for (int i = 0; i < 4; i++)
        #pragma unroll
        for (int j = 0; j < NT; j++)
            #pragma unroll
            for (int t = 0; t < 4; t++) acc[i][j][t] = 0.0f;

    auto load_chunk = [&](int ck, int st) {
        const int k0 = ck * 32;
        const u32 sa = sbase + (u32)st * STG;
        #pragma unroll
        for (int it = 0; it < 2; it++) {
            int a = tid + it * 256;
            int row = a >> 2, ch = a & 3;
            u32 dst = sa + (u32)row * ROWB + (u32)ch * 16;
            CP16(dst,        Ah + (size_t)(m0 + row) * lda + k0 + ch * 8);
            CP16(dst + A_LO, Al + (size_t)(m0 + row) * lda + k0 + ch * 8);
        }
        #pragma unroll
        for (int it = 0; it < BN / 64; it++) {
            int a = tid + it * 256;
            int row = a >> 2, ch = a & 3;
            u32 dst = sa + B_OFF + (u32)row * ROWB + (u32)ch * 16;
            CP16(dst,        Bh + (size_t)(n0 + row) * ldb + k0 + ch * 8);
            CP16(dst + B_LO, Bl + (size_t)(n0 + row) * ldb + k0 + ch * 8);
        }
    };

    auto compute = [&](int st) {
        const u32 ab  = sbase + (u32)st * STG;
        const u32 bb  = ab + B_OFF;
        const u32 rb  = (u32)((lane & 15) * ROWB);
        #pragma unroll
        for (int s16 = 0; s16 < 2; s16++) {
            const u32 coff = (u32)((s16 * 2 + (lane >> 4)) * 16);
            u32 ah[4][4], al[4][4];
            #pragma unroll
            for (int mt = 0; mt < 4; mt++) {
                u32 ad = ab + (u32)((wm * 64 + mt * 16) * ROWB) + rb + coff;
                LDSM4(ah[mt][0], ah[mt][1], ah[mt][2], ah[mt][3], ad);
                LDSM4(al[mt][0], al[mt][1], al[mt][2], al[mt][3], ad + A_LO);
            }
            u32 bh[NT][2], bl[NT][2];
            #pragma unroll
            for (int np = 0; np < NT / 2; np++) {
                u32 bd = bb + (u32)((wn * WN + np * 16) * ROWB) + rb + coff;
                u32 t0, t1, t2, t3;
                LDSM4(t0, t1, t2, t3, bd);
                bh[2*np][0] = t0; bh[2*np+1][0] = t1; bh[2*np][1] = t2; bh[2*np+1][1] = t3;
                LDSM4(t0, t1, t2, t3, bd + B_LO);
                bl[2*np][0] = t0; bl[2*np+1][0] = t1; bl[2*np][1] = t2; bl[2*np+1][1] = t3;
            }
            #pragma unroll
            for (int mt = 0; mt < 4; mt++)
                #pragma unroll
                for (int nt = 0; nt < NT; nt++) {
                    mma_bf16(acc[mt][nt], ah[mt], bh[nt]);
                    mma_bf16(acc[mt][nt], ah[mt], bl[nt]);
                    mma_bf16(acc[mt][nt], al[mt], bh[nt]);
                }
        }
    };

    const int NC = K >> 5;
    load_chunk(0, 0); CP_COMMIT();
    for (int i = 0; i < NC; i++) {
        if (i + 1 < NC) { load_chunk(i + 1, (i + 1) & 1); CP_COMMIT(); CP_WAIT1(); }
        else           { CP_WAIT0(); }
        __syncthreads();
        compute(i & 1);
        __syncthreads();
    }

    // -------- epilogue --------
    auto proc2 = [&](int gm, int gn, float v0, float v1) {
        v0 *= alpha; v1 *= alpha;
        if (EPI == 1 || EPI == 3) {
            float2 ad = *(const float2*)(addM + z * sAdd + (size_t)gm * ldadd + gn);
            v0 += ad.x; v1 += ad.y;
        }
        if (EPI == 2 || EPI == 3) {
            float2 bn2 = *(const float2*)(biasN + gn);
            v0 += bn2.x; v1 += bn2.y;
        }
        if (EPI == 2) {
            v0 = 0.5f * v0 * (1.0f + erff(v0 * 0.70710678118654752f));
            v1 = 0.5f * v1 * (1.0f + erff(v1 * 0.70710678118654752f));
        }
        if (OUTM == 0) {
            *(float2*)(C + z * sC + (size_t)gm * ldc + gn) = make_float2(v0, v1);
        } else {
            bf16 h0, l0, h1, l1;
            split2(v0, h0, l0); split2(v1, h1, l1);
            u32 hp = (u32)__bfloat16_as_ushort(h0) | ((u32)__bfloat16_as_ushort(h1) << 16);
            u32 lp = (u32)__bfloat16_as_ushort(l0) | ((u32)__bfloat16_as_ushort(l1) << 16);
            *(u32*)(Ch + z * sC + (size_t)gm * ldc + gn) = hp;
            *(u32*)(Cl + z * sC + (size_t)gm * ldc + gn) = lp;
        }
    };

    const int r  = lane >> 2;
    const int c2 = (lane & 3) * 2;
    #pragma unroll
    for (int mt = 0; mt < 4; mt++) {
        #pragma unroll
        for (int nt = 0; nt < NT; nt++) {
            int gm = m0 + wm * 64 + mt * 16 + r;
            int gn = n0 + wn * WN + nt * 8 + c2;
            proc2(gm,     gn, acc[mt][nt][0], acc[mt][nt][1]);
            proc2(gm + 8, gn, acc[mt][nt][2], acc[mt][nt][3]);
        }
    }
}

// ------------------- split fp32 -> (hi, lo) bf16 -------------------
__global__ __launch_bounds__(256)
void split_k(const float* __restrict__ x, bf16* __restrict__ h, bf16* __restrict__ l)
{
    size_t i = (size_t)blockIdx.x * 256 + threadIdx.x;
    float4 v = ((const float4*)x)[i];
    bf16 h0,l0,h1,l1,h2,l2,h3,l3;
    split2(v.x,h0,l0); split2(v.y,h1,l1); split2(v.z,h2,l2); split2(v.w,h3,l3);
    uint2 hp = make_uint2((u32)__bfloat16_as_ushort(h0) | ((u32)__bfloat16_as_ushort(h1)<<16),
                          (u32)__bfloat16_as_ushort(h2) | ((u32)__bfloat16_as_ushort(h3)<<16));
    uint2 lp = make_uint2((u32)__bfloat16_as_ushort(l0) | ((u32)__bfloat16_as_ushort(l1)<<16),
                          (u32)__bfloat16_as_ushort(l2) | ((u32)__bfloat16_as_ushort(l3)<<16));
    ((uint2*)h)[i] = hp;
    ((uint2*)l)[i] = lp;
}

// ------------------- V transpose + split: vt[b][d][s] = v[b][s][d] -------------------
__global__ void tsplit_k(const float* __restrict__ v, bf16* __restrict__ th, bf16* __restrict__ tl)
{
    __shared__ float t[32][33];
    const int b = blockIdx.z;
    const int d0 = blockIdx.x * 32, s0 = blockIdx.y * 32;
    const float* src = v + (size_t)b * SQ * DM;
    for (int j = threadIdx.y; j < 32; j += 8)
        t[j][threadIdx.x] = src[(size_t)(s0 + j) * DM + d0 + threadIdx.x];
    __syncthreads();
    bf16* oh = th + (size_t)b * DM * SQ;
    bf16* ol = tl + (size_t)b * DM * SQ;
    for (int j = threadIdx.y; j < 32; j += 8) {
        float x = t[threadIdx.x][j];
        bf16 h, l; split2(x, h, l);
        oh[(size_t)(d0 + j) * SQ + s0 + threadIdx.x] = h;
        ol[(size_t)(d0 + j) * SQ + s0 + threadIdx.x] = l;
    }
}

// ------------------- softmax rows of 2048 -> split bf16 -------------------
__global__ __launch_bounds__(256)
void softmax_k(const float* __restrict__ s, bf16* __restrict__ ph_, bf16* __restrict__ pl_)
{
    const float* p = s + (size_t)blockIdx.x * SQ;
    const int tid = threadIdx.x, lane = tid & 31, warp = tid >> 5;
    __shared__ float red[8];

    float v[8];
    float4 a = ((const float4*)p)[tid * 2];
    float4 b = ((const float4*)p)[tid * 2 + 1];
    v[0]=a.x; v[1]=a.y; v[2]=a.z; v[3]=a.w; v[4]=b.x; v[5]=b.y; v[6]=b.z; v[7]=b.w;
    float mx = -3.0e38f;
    #pragma unroll
    for (int i = 0; i < 8; i++) mx = fmaxf(mx, v[i]);
    #pragma unroll
    for (int o = 16; o; o >>= 1) mx = fmaxf(mx, __shfl_xor_sync(0xffffffffu, mx, o));
    if (!lane) red[warp] = mx;
    __syncthreads();
    mx = red[0];
    #pragma unroll
    for (int i = 1; i < 8; i++) mx = fmaxf(mx, red[i]);

    float sum = 0.0f;
    #pragma unroll
    for (int i = 0; i < 8; i++) { v[i] = expf(v[i] - mx); sum += v[i]; }
    #pragma unroll
    for (int o = 16; o; o >>= 1) sum += __shfl_xor_sync(0xffffffffu, sum, o);
    __syncthreads();
    if (!lane) red[warp] = sum;
    __syncthreads();
    sum = 0.0f;
    #pragma unroll
    for (int i = 0; i < 8; i++) sum += red[i];
    const float inv = 1.0f / sum;

    u32 hp[4], lp[4];
    #pragma unroll
    for (int j = 0; j < 4; j++) {
        bf16 h0,l0,h1,l1;
        split2(v[2*j] * inv, h0, l0);
        split2(v[2*j+1] * inv, h1, l1);
        hp[j] = (u32)__bfloat16_as_ushort(h0) | ((u32)__bfloat16_as_ushort(h1)<<16);
        lp[j] = (u32)__bfloat16_as_ushort(l0) | ((u32)__bfloat16_as_ushort(l1)<<16);
    }
    ((uint4*)(ph_ + (size_t)blockIdx.x * SQ))[tid] = make_uint4(hp[0],hp[1],hp[2],hp[3]);
    ((uint4*)(pl_ + (size_t)blockIdx.x * SQ))[tid] = make_uint4(lp[0],lp[1],lp[2],lp[3]);
}

// ------------------- LayerNorm rows of 1024 -------------------
template<int OUTM>   // 0: fp32 y; 1: split (yh, yl)
__global__ __launch_bounds__(256)
void ln_k(const float* __restrict__ x, float* __restrict__ y,
          bf16* __restrict__ yh, bf16* __restrict__ yl,
          const float* __restrict__ gg, const float* __restrict__ bb)
{
    const float* p = x + (size_t)blockIdx.x * DM;
    const int tid = threadIdx.x, lane = tid & 31, warp = tid >> 5;
    __shared__ float r1[8], r2[8];

    float4 v4 = ((const float4*)p)[tid];
    float v[4] = {v4.x, v4.y, v4.z, v4.w};
    float sm = v[0]+v[1]+v[2]+v[3];
    float s2 = v[0]*v[0]+v[1]*v[1]+v[2]*v[2]+v[3]*v[3];
    #pragma unroll
    for (int o = 16; o; o >>= 1) {
        sm += __shfl_xor_sync(0xffffffffu, sm, o);
        s2 += __shfl_xor_sync(0xffffffffu, s2, o);
    }
    if (!lane) { r1[warp] = sm; r2[warp] = s2; }
    __syncthreads();
    sm = 0.0f; s2 = 0.0f;
    #pragma unroll
    for (int i = 0; i < 8; i++) { sm += r1[i]; s2 += r2[i]; }
    const float mean = sm * (1.0f / DM);
    const float var  = s2 * (1.0f / DM) - mean * mean;
    const float inv  = rsqrtf(var + 1e-5f);

    float4 g4 = ((const float4*)gg)[tid];
    float4 b4 = ((const float4*)bb)[tid];
    float o0 = (v[0]-mean)*inv*g4.x + b4.x;
    float o1 = (v[1]-mean)*inv*g4.y + b4.y;
    float o2 = (v[2]-mean)*inv*g4.z + b4.z;
    float o3 = (v[3]-mean)*inv*g4.w + b4.w;
    if (OUTM == 0) {
        ((float4*)(y + (size_t)blockIdx.x * DM))[tid] = make_float4(o0,o1,o2,o3);
    } else {
        bf16 h0,l0,h1,l1,h2,l2,h3,l3;
        split2(o0,h0,l0); split2(o1,h1,l1); split2(o2,h2,l2); split2(o3,h3,l3);
        uint2 hp = make_uint2((u32)__bfloat16_as_ushort(h0) | ((u32)__bfloat16_as_ushort(h1)<<16),
                              (u32)__bfloat16_as_ushort(h2) | ((u32)__bfloat16_as_ushort(h3)<<16));
        uint2 lp = make_uint2((u32)__bfloat16_as_ushort(l0) | ((u32)__bfloat16_as_ushort(l1)<<16),
                              (u32)__bfloat16_as_ushort(l2) | ((u32)__bfloat16_as_ushort(l3)<<16));
        ((uint2*)(yh + (size_t)blockIdx.x * DM))[tid] = hp;
        ((uint2*)(yl + (size_t)blockIdx.x * DM))[tid] = lp;
    }
}

// ------------------- launch -------------------
#define SMEM128 (2 * (2*128 + 2*128) * 80)   // 81920
#define SMEM64  (2 * (2*128 + 2*64)  * 80)   // 61440

extern "C" void kernel_launch(void* const* d_in, const int* in_sizes, int n_in,
                              void* d_out, int out_size)
{
    const float* x_q  = (const float*)d_in[0];
    const float* x_kv = (const float*)d_in[1];
    const float* bias = (const float*)d_in[2];
    const float* Wq   = (const float*)d_in[3];
    const float* Wk   = (const float*)d_in[4];
    const float* Wv   = (const float*)d_in[5];
    const float* Wo   = (const float*)d_in[6];
    const float* W1   = (const float*)d_in[7];
    const float* b1   = (const float*)d_in[8];
    const float* W2   = (const float*)d_in[9];
    const float* b2   = (const float*)d_in[10];
    const float* g1   = (const float*)d_in[11];
    const float* be1  = (const float*)d_in[12];
    const float* g2   = (const float*)d_in[13];
    const float* be2  = (const float*)d_in[14];
    float* out = (float*)d_out;

    bf16 *xqh,*xql,*xkh,*xkl,*wqh,*wql,*wkh,*wkl,*wvh,*wvl,*woh,*wol,*w1h,*w1l,*w2h,*w2l;
    bf16 *qh,*ql,*kh,*kl,*vth,*vtl,*pH,*pL,*oh,*ol,*lnh,*lnl,*hH,*hL;
    float *vv,*sc,*x1,*x2;
    cudaGetSymbolAddress((void**)&xqh, s_xq_h); cudaGetSymbolAddress((void**)&xql, s_xq_l);
    cudaGetSymbolAddress((void**)&xkh, s_xk_h); cudaGetSymbolAddress((void**)&xkl, s_xk_l);
    cudaGetSymbolAddress((void**)&wqh, s_wq_h); cudaGetSymbolAddress((void**)&wql, s_wq_l);
    cudaGetSymbolAddress((void**)&wkh, s_wk_h); cudaGetSymbolAddress((void**)&wkl, s_wk_l);
    cudaGetSymbolAddress((void**)&wvh, s_wv_h); cudaGetSymbolAddress((void**)&wvl, s_wv_l);
    cudaGetSymbolAddress((void**)&woh, s_wo_h); cudaGetSymbolAddress((void**)&wol, s_wo_l);
    cudaGetSymbolAddress((void**)&w1h, s_w1_h); cudaGetSymbolAddress((void**)&w1l, s_w1_l);
    cudaGetSymbolAddress((void**)&w2h, s_w2_h); cudaGetSymbolAddress((void**)&w2l, s_w2_l);
    cudaGetSymbolAddress((void**)&qh,  s_q_h);  cudaGetSymbolAddress((void**)&ql,  s_q_l);
    cudaGetSymbolAddress((void**)&kh,  s_k_h);  cudaGetSymbolAddress((void**)&kl,  s_k_l);
    cudaGetSymbolAddress((void**)&vv,  s_v);
    cudaGetSymbolAddress((void**)&vth, s_vt_h); cudaGetSymbolAddress((void**)&vtl, s_vt_l);
    cudaGetSymbolAddress((void**)&sc,  s_sc);
    cudaGetSymbolAddress((void**)&pH,  s_p_h);  cudaGetSymbolAddress((void**)&pL,  s_p_l);
    cudaGetSymbolAddress((void**)&oh,  s_o_h);  cudaGetSymbolAddress((void**)&ol,  s_o_l);
    cudaGetSymbolAddress((void**)&x1,  s_x1);
    cudaGetSymbolAddress((void**)&lnh, s_ln_h); cudaGetSymbolAddress((void**)&lnl, s_ln_l);
    cudaGetSymbolAddress((void**)&hH,  s_hh);   cudaGetSymbolAddress((void**)&hL,  s_hl);
    cudaGetSymbolAddress((void**)&x2,  s_x2);

    cudaFuncSetAttribute(gemm_mma<0,1,128>, cudaFuncAttributeMaxDynamicSharedMemorySize, SMEM128);
    cudaFuncSetAttribute(gemm_mma<0,0,128>, cudaFuncAttributeMaxDynamicSharedMemorySize, SMEM128);
    cudaFuncSetAttribute(gemm_mma<1,0,128>, cudaFuncAttributeMaxDynamicSharedMemorySize, SMEM128);
    cudaFuncSetAttribute(gemm_mma<2,1,128>, cudaFuncAttributeMaxDynamicSharedMemorySize, SMEM128);
    cudaFuncSetAttribute(gemm_mma<3,0,128>, cudaFuncAttributeMaxDynamicSharedMemorySize, SMEM128);
    cudaFuncSetAttribute(gemm_mma<0,1,64>,  cudaFuncAttributeMaxDynamicSharedMemorySize, SMEM64);

    const long long SD  = (long long)SQ * DM;
    const long long SS2 = (long long)SQ * SQ;

    // splits of inputs and weights
    split_k<<<MR*DM/1024, 256>>>(x_q,  xqh, xql);
    split_k<<<MR*DM/1024, 256>>>(x_kv, xkh, xkl);
    split_k<<<DM*DM/1024, 256>>>(Wq, wqh, wql);
    split_k<<<DM*DM/1024, 256>>>(Wk, wkh, wkl);
    split_k<<<DM*DM/1024, 256>>>(Wv, wvh, wvl);
    split_k<<<DM*DM/1024, 256>>>(Wo, woh, wol);
    split_k<<<FF*DM/1024, 256>>>(W1, w1h, w1l);
    split_k<<<DM*FF/1024, 256>>>(W2, w2h, w2l);

    // Q, K projections (split out), V (fp32 out)
    {
        dim3 gr(DM/128, MR/128, 1);
        gemm_mma<0,1,128><<<gr, 256, SMEM128>>>(xqh, xql, wqh, wql, nullptr, qh, ql,
            DM, DM, DM, DM, 0, 0, 0, 1.0f, nullptr, 0, 0, nullptr);
        gemm_mma<0,1,128><<<gr, 256, SMEM128>>>(xkh, xkl, wkh, wkl, nullptr, kh, kl,
            DM, DM, DM, DM, 0, 0, 0, 1.0f, nullptr, 0, 0, nullptr);
        gemm_mma<0,0,128><<<gr, 256, SMEM128>>>(xkh, xkl, wvh, wvl, vv, nullptr, nullptr,
            DM, DM, DM, DM, 0, 0, 0, 1.0f, nullptr, 0, 0, nullptr);
    }
    tsplit_k<<<dim3(DM/32, SQ/32, BB), dim3(32, 8)>>>(vv, vth, vtl);

    // scores = Q K^T / 8 + bias  (per batch; z = head, A/B head stride = 64 elements)
    for (int b = 0; b < BB; b++) {
        dim3 gr(SQ/128, SQ/128, NHD);
        gemm_mma<1,0,128><<<gr, 256, SMEM128>>>(
            qh + (size_t)b*SD, ql + (size_t)b*SD, kh + (size_t)b*SD, kl + (size_t)b*SD,
            sc + (size_t)b*NHD*SS2, nullptr, nullptr,
            64, DM, DM, SQ, 64, 64, SS2, 0.125f,
            bias + (size_t)b*NHD*SS2, SQ, SS2, nullptr);
    }

    softmax_k<<<BB*NHD*SQ, 256>>>(sc, pH, pL);

    // O_h = P @ V_h  (NT with V^T; z = head)
    for (int b = 0; b < BB; b++) {
        dim3 gr(1, SQ/128, NHD);
        gemm_mma<0,1,64><<<gr, 256, SMEM64>>>(
            pH + (size_t)b*NHD*SS2, pL + (size_t)b*NHD*SS2,
            vth + (size_t)b*DM*SQ, vtl + (size_t)b*DM*SQ,
            nullptr, oh + (size_t)b*SD, ol + (size_t)b*SD,
            SQ, SQ, SQ, DM, SS2, (long long)64*SQ, 64, 1.0f, nullptr, 0, 0, nullptr);
    }

    // x1 = x_q + O @ Wo^T
    gemm_mma<1,0,128><<<dim3(DM/128, MR/128, 1), 256, SMEM128>>>(
        oh, ol, woh, wol, x1, nullptr, nullptr,
        DM, DM, DM, DM, 0, 0, 0, 1.0f, x_q, DM, 0, nullptr);

    ln_k<1><<<MR, 256>>>(x1, nullptr, lnh, lnl, g1, be1);

    // h = gelu(ln1 @ W1^T + b1)  (split out)
    gemm_mma<2,1,128><<<dim3(FF/128, MR/128, 1), 256, SMEM128>>>(
        lnh, lnl, w1h, w1l, nullptr, hH, hL,
        DM, DM, DM, FF, 0, 0, 0, 1.0f, nullptr, 0, 0, b1);

    // x2 = x1 + h @ W2^T + b2
    gemm_mma<3,0,128><<<dim3(DM/128, MR/128, 1), 256, SMEM128>>>(
        hH, hL, w2h, w2l, x2, nullptr, nullptr,
        FF, FF, FF, DM, 0, 0, 0, 1.0f, x1, DM, 0, b2);

    ln_k<0><<<MR, 256>>>(x2, out, nullptr, nullptr, g2, be2);
}

// round 6
// speedup vs baseline: 2.3577x; 1.1508x over previous
#include <cuda_runtime.h>
#include <cuda_bf16.h>
#include <cstdint>
#include <math.h>

typedef __nv_bfloat16 bf16;
typedef unsigned int u32;

#define BB 2
#define SQ 2048
#define DM 1024
#define NHD 16
#define FF 4096
#define MR (BB*SQ)

// ------------------- scratch (device globals) -------------------
__device__ bf16 s_xq_h[MR*DM], s_xq_l[MR*DM];
__device__ bf16 s_xk_h[MR*DM], s_xk_l[MR*DM];
__device__ bf16 s_wq_h[DM*DM], s_wq_l[DM*DM];
__device__ bf16 s_wk_h[DM*DM], s_wk_l[DM*DM];
__device__ bf16 s_wv_h[DM*DM], s_wv_l[DM*DM];
__device__ bf16 s_wo_h[DM*DM], s_wo_l[DM*DM];
__device__ bf16 s_w1_h[FF*DM], s_w1_l[FF*DM];
__device__ bf16 s_w2_h[DM*FF], s_w2_l[DM*FF];
__device__ bf16 s_q_h[MR*DM],  s_q_l[MR*DM];
__device__ bf16 s_k_h[MR*DM],  s_k_l[MR*DM];
__device__ bf16 s_v_h[MR*DM],  s_v_l[MR*DM];
__device__ bf16 s_o_h[MR*DM],  s_o_l[MR*DM];
__device__ float s_x1[MR*DM];
__device__ bf16 s_ln_h[MR*DM], s_ln_l[MR*DM];
__device__ bf16 s_hh[(size_t)MR*FF], s_hl[(size_t)MR*FF];
__device__ float s_x2[MR*DM];

// ------------------- helpers -------------------
__device__ __forceinline__ u32 smem_u32(const void* p) {
    return (u32)__cvta_generic_to_shared(p);
}
#define CP16(dst, src) \
    asm volatile("cp.async.cg.shared.global [%0], [%1], 16;" :: "r"(dst), "l"(src))
#define CP_COMMIT() asm volatile("cp.async.commit_group;" ::: "memory")
#define CP_WAIT1()  asm volatile("cp.async.wait_group 1;" ::: "memory")
#define CP_WAIT0()  asm volatile("cp.async.wait_group 0;" ::: "memory")

#define LDSM4(r0, r1, r2, r3, addr) \
    asm volatile("ldmatrix.sync.aligned.m8n8.x4.shared.b16 {%0,%1,%2,%3}, [%4];" \
        : "=r"(r0), "=r"(r1), "=r"(r2), "=r"(r3) : "r"(addr))
#define LDSM4T(r0, r1, r2, r3, addr) \
    asm volatile("ldmatrix.sync.aligned.m8n8.x4.trans.shared.b16 {%0,%1,%2,%3}, [%4];" \
        : "=r"(r0), "=r"(r1), "=r"(r2), "=r"(r3) : "r"(addr))

__device__ __forceinline__ void mma_bf16(float* c, const u32* a, const u32* b) {
    asm volatile("mma.sync.aligned.m16n8k16.row.col.f32.bf16.bf16.f32 "
        "{%0,%1,%2,%3}, {%4,%5,%6,%7}, {%8,%9}, {%0,%1,%2,%3};"
        : "+f"(c[0]), "+f"(c[1]), "+f"(c[2]), "+f"(c[3])
        : "r"(a[0]), "r"(a[1]), "r"(a[2]), "r"(a[3]), "r"(b[0]), "r"(b[1]));
}

__device__ __forceinline__ void split2(float v, bf16& h, bf16& l) {
    h = __float2bfloat16(v);
    l = __float2bfloat16(v - __bfloat162float(h));
}
__device__ __forceinline__ u32 packbf(float a, float b) {
    return (u32)__bfloat16_as_ushort(__float2bfloat16(a)) |
           ((u32)__bfloat16_as_ushort(__float2bfloat16(b)) << 16);
}

// ------------------- HMMA GEMM (3-stage pipeline) -------------------
// C[m,n] = alpha * sum_k A[m,k]*B[n,k] (+ epilogue); A/B bf16 hi/lo splits (K-major).
// EPI: 0 none; 1 +addM; 2 +biasN then GELU; 3 +addM +biasN
// OUTM: 0 -> fp32 C; 1 -> split bf16 (Ch, Cl)
// BM=128, BN=128, BK=32. 256 threads, warps 2(M)x4(N).
template<int EPI, int OUTM>
__global__ __launch_bounds__(256, 1)
void gemm_mma(const bf16* __restrict__ Ah, const bf16* __restrict__ Al,
              const bf16* __restrict__ Bh, const bf16* __restrict__ Bl,
              float* __restrict__ C, bf16* __restrict__ Ch, bf16* __restrict__ Cl,
              int K, int lda, int ldb, int ldc,
              long long sA, long long sB, long long sC,
              float alpha,
              const float* __restrict__ addM, int ldadd, long long sAdd,
              const float* __restrict__ biasN)
{
    constexpr int BN = 128;
    constexpr int WN  = BN / 4;
    constexpr int NT  = WN / 8;
    constexpr u32 ROWB  = 80;
    constexpr u32 A_LO  = 128 * ROWB;
    constexpr u32 B_OFF = 2 * 128 * ROWB;
    constexpr u32 B_LO  = (u32)BN * ROWB;
    constexpr u32 STG   = (2 * 128 + 2 * BN) * ROWB;

    extern __shared__ char smem[];
    const u32 sbase = smem_u32(smem);
    const int tid = threadIdx.x, lane = tid & 31, wid = tid >> 5;
    const int wm = wid & 1, wn = wid >> 1;
    const long long z = blockIdx.z;

    Ah += z * sA;  Al += z * sA;
    Bh += z * sB;  Bl += z * sB;

    const int m0 = blockIdx.y * 128, n0 = blockIdx.x * BN;

    float acc[4][NT][4];
    #pragma unroll
    for (int i = 0; i < 4; i++)
        #pragma unroll
        for (int j = 0; j < NT; j++)
            #pragma unroll
            for (int t = 0; t < 4; t++) acc[i][j][t] = 0.0f;

    auto load_chunk = [&](int ck, int st) {
        const int k0 = ck * 32;
        const u32 sa = sbase + (u32)st * STG;
        #pragma unroll
        for (int it = 0; it < 2; it++) {
            int a = tid + it * 256;
            int row = a >> 2, ch = a & 3;
            u32 dst = sa + (u32)row * ROWB + (u32)ch * 16;
            CP16(dst,        Ah + (size_t)(m0 + row) * lda + k0 + ch * 8);
            CP16(dst + A_LO, Al + (size_t)(m0 + row) * lda + k0 + ch * 8);
        }
        #pragma unroll
        for (int it = 0; it < 2; it++) {
            int a = tid + it * 256;
            int row = a >> 2, ch = a & 3;
            u32 dst = sa + B_OFF + (u32)row * ROWB + (u32)ch * 16;
            CP16(dst,        Bh + (size_t)(n0 + row) * ldb + k0 + ch * 8);
            CP16(dst + B_LO, Bl + (size_t)(n0 + row) * ldb + k0 + ch * 8);
        }
    };

    auto compute = [&](int st) {
        const u32 ab  = sbase + (u32)st * STG;
        const u32 bb  = ab + B_OFF;
        const u32 rb  = (u32)((lane & 15) * ROWB);
        #pragma unroll
        for (int s16 = 0; s16 < 2; s16++) {
            const u32 coff = (u32)((s16 * 2 + (lane >> 4)) * 16);
            u32 ah[4][4], al[4][4];
            #pragma unroll
            for (int mt = 0; mt < 4; mt++) {
                u32 ad = ab + (u32)((wm * 64 + mt * 16) * ROWB) + rb + coff;
                LDSM4(ah[mt][0], ah[mt][1], ah[mt][2], ah[mt][3], ad);
                LDSM4(al[mt][0], al[mt][1], al[mt][2], al[mt][3], ad + A_LO);
            }
            u32 bh[NT][2], bl[NT][2];
            #pragma unroll
            for (int np = 0; np < NT / 2; np++) {
                u32 bd = bb + (u32)((wn * WN + np * 16) * ROWB) + rb + coff;
                u32 t0, t1, t2, t3;
                LDSM4(t0, t1, t2, t3, bd);
                bh[2*np][0] = t0; bh[2*np+1][0] = t1; bh[2*np][1] = t2; bh[2*np+1][1] = t3;
                LDSM4(t0, t1, t2, t3, bd + B_LO);
                bl[2*np][0] = t0; bl[2*np+1][0] = t1; bl[2*np][1] = t2; bl[2*np+1][1] = t3;
            }
            #pragma unroll
            for (int mt = 0; mt < 4; mt++)
                #pragma unroll
                for (int nt = 0; nt < NT; nt++) {
                    mma_bf16(acc[mt][nt], ah[mt], bh[nt]);
                    mma_bf16(acc[mt][nt], ah[mt], bl[nt]);
                    mma_bf16(acc[mt][nt], al[mt], bh[nt]);
                }
        }
    };

    const int NC = K >> 5;
    load_chunk(0, 0); CP_COMMIT();
    load_chunk(1, 1); CP_COMMIT();
    for (int i = 0; i < NC; i++) {
        if (i + 1 < NC) CP_WAIT1(); else CP_WAIT0();
        __syncthreads();
        if (i + 2 < NC) { load_chunk(i + 2, (i + 2) % 3); CP_COMMIT(); }
        compute(i % 3);
    }

    // -------- epilogue --------
    auto proc2 = [&](int gm, int gn, float v0, float v1) {
        v0 *= alpha; v1 *= alpha;
        if (EPI == 1 || EPI == 3) {
            float2 ad = *(const float2*)(addM + z * sAdd + (size_t)gm * ldadd + gn);
            v0 += ad.x; v1 += ad.y;
        }
        if (EPI == 2 || EPI == 3) {
            float2 bn2 = *(const float2*)(biasN + gn);
            v0 += bn2.x; v1 += bn2.y;
        }
        if (EPI == 2) {
            v0 = 0.5f * v0 * (1.0f + erff(v0 * 0.70710678118654752f));
            v1 = 0.5f * v1 * (1.0f + erff(v1 * 0.70710678118654752f));
        }
        if (OUTM == 0) {
            *(float2*)(C + z * sC + (size_t)gm * ldc + gn) = make_float2(v0, v1);
        } else {
            bf16 h0, l0, h1, l1;
            split2(v0, h0, l0); split2(v1, h1, l1);
            u32 hp = (u32)__bfloat16_as_ushort(h0) | ((u32)__bfloat16_as_ushort(h1) << 16);
            u32 lp = (u32)__bfloat16_as_ushort(l0) | ((u32)__bfloat16_as_ushort(l1) << 16);
            *(u32*)(Ch + z * sC + (size_t)gm * ldc + gn) = hp;
            *(u32*)(Cl + z * sC + (size_t)gm * ldc + gn) = lp;
        }
    };

    const int r  = lane >> 2;
    const int c2 = (lane & 3) * 2;
    #pragma unroll
    for (int mt = 0; mt < 4; mt++) {
        #pragma unroll
        for (int nt = 0; nt < NT; nt++) {
            int gm = m0 + wm * 64 + mt * 16 + r;
            int gn = n0 + wn * WN + nt * 8 + c2;
            proc2(gm,     gn, acc[mt][nt][0], acc[mt][nt][1]);
            proc2(gm + 8, gn, acc[mt][nt][2], acc[mt][nt][3]);
        }
    }
}

// ------------------- fused flash attention -------------------
// grid (SQ/128, NHD, BB), 256 threads (8 warps x m16 rows).
// O[b, q, h*64+d] = softmax(Q K^T / 8 + bias) V, split bf16 out.
__global__ __launch_bounds__(256, 1)
void flash_k(const bf16* __restrict__ qh, const bf16* __restrict__ ql,
             const bf16* __restrict__ kh, const bf16* __restrict__ kl,
             const bf16* __restrict__ vh, const bf16* __restrict__ vl,
             const float* __restrict__ bias,
             bf16* __restrict__ oh, bf16* __restrict__ ol)
{
    constexpr u32 ROWB = 144;            // 64 bf16 = 128B + 16 pad
    constexpr u32 HKV  = 64 * ROWB;      // 9216 per half tile
    constexpr u32 STG  = 4 * HKV;        // Khi,Klo,Vhi,Vlo = 36864

    extern __shared__ char smem[];
    const u32 sbase = smem_u32(smem);
    const int tid = threadIdx.x, lane = tid & 31, wid = tid >> 5;
    const int b = blockIdx.z, h = blockIdx.y, q0 = blockIdx.x * 128;

    const size_t qbase = ((size_t)b * SQ + q0) * DM + h * 64;
    const size_t kvbase = (size_t)b * SQ * DM + h * 64;
    const float* bptr = bias + ((size_t)(b * NHD + h)) * SQ * SQ;

    // ---- stage Q into smem (reuse stage 0), then ldmatrix to registers ----
    #pragma unroll
    for (int it = 0; it < 4; it++) {
        int idx = tid + it * 256;            // 0..1023
        int row = idx >> 3, c8 = idx & 7;
        u32 dst = sbase + (u32)row * ROWB + (u32)c8 * 16;
        CP16(dst,            qh + qbase + (size_t)row * DM + c8 * 8);
        CP16(dst + 128*ROWB, ql + qbase + (size_t)row * DM + c8 * 8);
    }
    CP_COMMIT(); CP_WAIT0();
    __syncthreads();

    u32 qhf[4][4], qlf[4][4];
    {
        const u32 base = sbase + (u32)((wid * 16 + (lane & 15)) * ROWB);
        #pragma unroll
        for (int kq = 0; kq < 4; kq++) {
            u32 ad = base + (u32)(kq * 32 + (lane >> 4) * 16);
            LDSM4(qhf[kq][0], qhf[kq][1], qhf[kq][2], qhf[kq][3], ad);
            LDSM4(qlf[kq][0], qlf[kq][1], qlf[kq][2], qlf[kq][3], ad + 128*ROWB);
        }
    }
    __syncthreads();

    auto load_kv = [&](int ck, u32 st) {
        const int kv0 = ck * 64;
        #pragma unroll
        for (int it = 0; it < 2; it++) {
            int idx = tid + it * 256;        // 0..511
            int row = idx >> 3, c8 = idx & 7;
            size_t g = kvbase + (size_t)(kv0 + row) * DM + c8 * 8;
            u32 dst = st + (u32)row * ROWB + (u32)c8 * 16;
            CP16(dst,           kh + g);
            CP16(dst + HKV,     kl + g);
            CP16(dst + 2*HKV,   vh + g);
            CP16(dst + 3*HKV,   vl + g);
        }
    };

    float o[8][4];
    #pragma unroll
    for (int d = 0; d < 8; d++)
        #pragma unroll
        for (int t = 0; t < 4; t++) o[d][t] = 0.0f;
    float rm0 = -1e30f, rm1 = -1e30f, rs0 = 0.0f, rs1 = 0.0f;

    load_kv(0, sbase); CP_COMMIT();

    const u32 rbA = (u32)((lane & 15) * ROWB);
    const int g4  = lane >> 2, t4 = lane & 3;

    for (int ck = 0; ck < SQ / 64; ck++) {
        const u32 st = sbase + (u32)(ck & 1) * STG;
        if (ck + 1 < SQ / 64) { load_kv(ck + 1, sbase + (u32)((ck + 1) & 1) * STG); CP_COMMIT(); CP_WAIT1(); }
        else                  { CP_WAIT0(); }
        __syncthreads();

        // ---- S = Q K^T (3-term) ----
        float S[8][4];
        #pragma unroll
        for (int j = 0; j < 8; j++)
            #pragma unroll
            for (int t = 0; t < 4; t++) S[j][t] = 0.0f;

        #pragma unroll
        for (int kq = 0; kq < 4; kq++) {
            const u32 coff = (u32)(kq * 32 + (lane >> 4) * 16);
            #pragma unroll
            for (int jp = 0; jp < 4; jp++) {
                u32 kd = st + (u32)(jp * 16 * ROWB) + rbA + coff;
                u32 t0, t1, t2, t3;
                u32 bh[2][2], bl[2][2];
                LDSM4(t0, t1, t2, t3, kd);
                bh[0][0] = t0; bh[1][0] = t1; bh[0][1] = t2; bh[1][1] = t3;
                LDSM4(t0, t1, t2, t3, kd + HKV);
                bl[0][0] = t0; bl[1][0] = t1; bl[0][1] = t2; bl[1][1] = t3;
                #pragma unroll
                for (int u = 0; u < 2; u++) {
                    mma_bf16(S[2*jp+u], qhf[kq], bh[u]);
                    mma_bf16(S[2*jp+u], qhf[kq], bl[u]);
                    mma_bf16(S[2*jp+u], qlf[kq], bh[u]);
                }
            }
        }

        // ---- scale + bias ----
        const int kv0 = ck * 64;
        const int row0 = q0 + wid * 16 + g4;
        #pragma unroll
        for (int j = 0; j < 8; j++) {
            const int col = kv0 + j * 8 + t4 * 2;
            float2 bz0 = *(const float2*)(bptr + (size_t)row0 * SQ + col);
            float2 bz1 = *(const float2*)(bptr + (size_t)(row0 + 8) * SQ + col);
            S[j][0] = S[j][0] * 0.125f + bz0.x;
            S[j][1] = S[j][1] * 0.125f + bz0.y;
            S[j][2] = S[j][2] * 0.125f + bz1.x;
            S[j][3] = S[j][3] * 0.125f + bz1.y;
        }

        // ---- online softmax ----
        float m0 = -1e30f, m1 = -1e30f;
        #pragma unroll
        for (int j = 0; j < 8; j++) {
            m0 = fmaxf(m0, fmaxf(S[j][0], S[j][1]));
            m1 = fmaxf(m1, fmaxf(S[j][2], S[j][3]));
        }
        m0 = fmaxf(m0, __shfl_xor_sync(0xffffffffu, m0, 1));
        m0 = fmaxf(m0, __shfl_xor_sync(0xffffffffu, m0, 2));
        m1 = fmaxf(m1, __shfl_xor_sync(0xffffffffu, m1, 1));
        m1 = fmaxf(m1, __shfl_xor_sync(0xffffffffu, m1, 2));
        const float nm0 = fmaxf(rm0, m0), nm1 = fmaxf(rm1, m1);
        const float f0 = expf(rm0 - nm0), f1 = expf(rm1 - nm1);
        float ls0 = 0.0f, ls1 = 0.0f;
        #pragma unroll
        for (int j = 0; j < 8; j++) {
            S[j][0] = expf(S[j][0] - nm0); ls0 += S[j][0];
            S[j][1] = expf(S[j][1] - nm0); ls0 += S[j][1];
            S[j][2] = expf(S[j][2] - nm1); ls1 += S[j][2];
            S[j][3] = expf(S[j][3] - nm1); ls1 += S[j][3];
        }
        rs0 = rs0 * f0 + ls0;
        rs1 = rs1 * f1 + ls1;
        rm0 = nm0; rm1 = nm1;
        #pragma unroll
        for (int d = 0; d < 8; d++) {
            o[d][0] *= f0; o[d][1] *= f0; o[d][2] *= f1; o[d][3] *= f1;
        }

        // ---- pack P hi/lo A-fragments ----
        u32 pa[4][4], pb[4][4];
        #pragma unroll
        for (int kp = 0; kp < 4; kp++) {
            float v00 = S[2*kp][0],   v01 = S[2*kp][1];
            float v10 = S[2*kp][2],   v11 = S[2*kp][3];
            float v20 = S[2*kp+1][0], v21 = S[2*kp+1][1];
            float v30 = S[2*kp+1][2], v31 = S[2*kp+1][3];
            bf16 h, l;
            bf16 h00,l00,h01,l01,h10,l10,h11,l11,h20,l20,h21,l21,h30,l30,h31,l31;
            split2(v00,h00,l00); split2(v01,h01,l01);
            split2(v10,h10,l10); split2(v11,h11,l11);
            split2(v20,h20,l20); split2(v21,h21,l21);
            split2(v30,h30,l30); split2(v31,h31,l31);
            (void)h; (void)l;
            pa[kp][0] = (u32)__bfloat16_as_ushort(h00) | ((u32)__bfloat16_as_ushort(h01) << 16);
            pa[kp][1] = (u32)__bfloat16_as_ushort(h10) | ((u32)__bfloat16_as_ushort(h11) << 16);
            pa[kp][2] = (u32)__bfloat16_as_ushort(h20) | ((u32)__bfloat16_as_ushort(h21) << 16);
            pa[kp][3] = (u32)__bfloat16_as_ushort(h30) | ((u32)__bfloat16_as_ushort(h31) << 16);
            pb[kp][0] = (u32)__bfloat16_as_ushort(l00) | ((u32)__bfloat16_as_ushort(l01) << 16);
            pb[kp][1] = (u32)__bfloat16_as_ushort(l10) | ((u32)__bfloat16_as_ushort(l11) << 16);
            pb[kp][2] = (u32)__bfloat16_as_ushort(l20) | ((u32)__bfloat16_as_ushort(l21) << 16);
            pb[kp][3] = (u32)__bfloat16_as_ushort(l30) | ((u32)__bfloat16_as_ushort(l31) << 16);
        }

        // ---- O += P V (3-term), V via ldmatrix.trans ----
        const u32 vbase = st + 2 * HKV;
        const u32 vrow  = (u32)((lane & 7) + 8 * ((lane >> 3) & 1));
        const u32 vcolb = (u32)((lane >> 4) * 16);     // 8 elems * 2B
        #pragma unroll
        for (int kp = 0; kp < 4; kp++) {
            #pragma unroll
            for (int dp = 0; dp < 4; dp++) {
                u32 vd = vbase + (u32)((kp * 16 + vrow) * ROWB) + (u32)(dp * 32) + vcolb;
                u32 r0, r1, r2, r3;
                u32 vhf[2][2], vlf[2][2];
                LDSM4T(r0, r1, r2, r3, vd);
                vhf[0][0] = r0; vhf[0][1] = r1; vhf[1][0] = r2; vhf[1][1] = r3;
                LDSM4T(r0, r1, r2, r3, vd + HKV);
                vlf[0][0] = r0; vlf[0][1] = r1; vlf[1][0] = r2; vlf[1][1] = r3;
                #pragma unroll
                for (int u = 0; u < 2; u++) {
                    mma_bf16(o[2*dp+u], pa[kp], vhf[u]);
                    mma_bf16(o[2*dp+u], pb[kp], vhf[u]);
                    mma_bf16(o[2*dp+u], pa[kp], vlf[u]);
                }
            }
        }
        __syncthreads();
    }

    // ---- finalize ----
    rs0 += __shfl_xor_sync(0xffffffffu, rs0, 1);
    rs0 += __shfl_xor_sync(0xffffffffu, rs0, 2);
    rs1 += __shfl_xor_sync(0xffffffffu, rs1, 1);
    rs1 += __shfl_xor_sync(0xffffffffu, rs1, 2);
    const float i0 = 1.0f / rs0, i1 = 1.0f / rs1;
    const int row0 = q0 + wid * 16 + g4;
    #pragma unroll
    for (int d = 0; d < 8; d++) {
        const int col = h * 64 + d * 8 + t4 * 2;
        bf16 h0, l0, h1, l1;
        split2(o[d][0] * i0, h0, l0); split2(o[d][1] * i0, h1, l1);
        *(u32*)(oh + ((size_t)b * SQ + row0) * DM + col) =
            (u32)__bfloat16_as_ushort(h0) | ((u32)__bfloat16_as_ushort(h1) << 16);
        *(u32*)(ol + ((size_t)b * SQ + row0) * DM + col) =
            (u32)__bfloat16_as_ushort(l0) | ((u32)__bfloat16_as_ushort(l1) << 16);
        split2(o[d][2] * i1, h0, l0); split2(o[d][3] * i1, h1, l1);
        *(u32*)(oh + ((size_t)b * SQ + row0 + 8) * DM + col) =
            (u32)__bfloat16_as_ushort(h0) | ((u32)__bfloat16_as_ushort(h1) << 16);
        *(u32*)(ol + ((size_t)b * SQ + row0 + 8) * DM + col) =
            (u32)__bfloat16_as_ushort(l0) | ((u32)__bfloat16_as_ushort(l1) << 16);
    }
}

// ------------------- split fp32 -> (hi, lo) bf16 -------------------
__global__ __launch_bounds__(256)
void split_k(const float* __restrict__ x, bf16* __restrict__ h, bf16* __restrict__ l)
{
    size_t i = (size_t)blockIdx.x * 256 + threadIdx.x;
    float4 v = ((const float4*)x)[i];
    bf16 h0,l0,h1,l1,h2,l2,h3,l3;
    split2(v.x,h0,l0); split2(v.y,h1,l1); split2(v.z,h2,l2); split2(v.w,h3,l3);
    uint2 hp = make_uint2((u32)__bfloat16_as_ushort(h0) | ((u32)__bfloat16_as_ushort(h1)<<16),
                          (u32)__bfloat16_as_ushort(h2) | ((u32)__bfloat16_as_ushort(h3)<<16));
    uint2 lp = make_uint2((u32)__bfloat16_as_ushort(l0) | ((u32)__bfloat16_as_ushort(l1)<<16),
                          (u32)__bfloat16_as_ushort(l2) | ((u32)__bfloat16_as_ushort(l3)<<16));
    ((uint2*)h)[i] = hp;
    ((uint2*)l)[i] = lp;
}

// ------------------- LayerNorm rows of 1024 -------------------
template<int OUTM>   // 0: fp32 y; 1: split (yh, yl)
__global__ __launch_bounds__(256)
void ln_k(const float* __restrict__ x, float* __restrict__ y,
          bf16* __restrict__ yh, bf16* __restrict__ yl,
          const float* __restrict__ gg, const float* __restrict__ bb)
{
    const float* p = x + (size_t)blockIdx.x * DM;
    const int tid = threadIdx.x, lane = tid & 31, warp = tid >> 5;
    __shared__ float r1[8], r2[8];

    float4 v4 = ((const float4*)p)[tid];
    float v[4] = {v4.x, v4.y, v4.z, v4.w};
    float sm = v[0]+v[1]+v[2]+v[3];
    float s2 = v[0]*v[0]+v[1]*v[1]+v[2]*v[2]+v[3]*v[3];
    #pragma unroll
    for (int o = 16; o; o >>= 1) {
        sm += __shfl_xor_sync(0xffffffffu, sm, o);
        s2 += __shfl_xor_sync(0xffffffffu, s2, o);
    }
    if (!lane) { r1[warp] = sm; r2[warp] = s2; }
    __syncthreads();
    sm = 0.0f; s2 = 0.0f;
    #pragma unroll
    for (int i = 0; i < 8; i++) { sm += r1[i]; s2 += r2[i]; }
    const float mean = sm * (1.0f / DM);
    const float var  = s2 * (1.0f / DM) - mean * mean;
    const float inv  = rsqrtf(var + 1e-5f);

    float4 g4 = ((const float4*)gg)[tid];
    float4 b4 = ((const float4*)bb)[tid];
    float o0 = (v[0]-mean)*inv*g4.x + b4.x;
    float o1 = (v[1]-mean)*inv*g4.y + b4.y;
    float o2 = (v[2]-mean)*inv*g4.z + b4.z;
    float o3 = (v[3]-mean)*inv*g4.w + b4.w;
    if (OUTM == 0) {
        ((float4*)(y + (size_t)blockIdx.x * DM))[tid] = make_float4(o0,o1,o2,o3);
    } else {
        bf16 h0,l0,h1,l1,h2,l2,h3,l3;
        split2(o0,h0,l0); split2(o1,h1,l1); split2(o2,h2,l2); split2(o3,h3,l3);
        uint2 hp = make_uint2((u32)__bfloat16_as_ushort(h0) | ((u32)__bfloat16_as_ushort(h1)<<16),
                              (u32)__bfloat16_as_ushort(h2) | ((u32)__bfloat16_as_ushort(h3)<<16));
        uint2 lp = make_uint2((u32)__bfloat16_as_ushort(l0) | ((u32)__bfloat16_as_ushort(l1)<<16),
                              (u32)__bfloat16_as_ushort(l2) | ((u32)__bfloat16_as_ushort(l3)<<16));
        ((uint2*)(yh + (size_t)blockIdx.x * DM))[tid] = hp;
        ((uint2*)(yl + (size_t)blockIdx.x * DM))[tid] = lp;
    }
}

// ------------------- launch -------------------
#define SMEM_GEMM (3 * (2*128 + 2*128) * 80)   // 122880
#define SMEM_FLASH (2 * 4 * 64 * 144)          // 73728

extern "C" void kernel_launch(void* const* d_in, const int* in_sizes, int n_in,
                              void* d_out, int out_size)
{
    const float* x_q  = (const float*)d_in[0];
    const float* x_kv = (const float*)d_in[1];
    const float* bias = (const float*)d_in[2];
    const float* Wq   = (const float*)d_in[3];
    const float* Wk   = (const float*)d_in[4];
    const float* Wv   = (const float*)d_in[5];
    const float* Wo   = (const float*)d_in[6];
    const float* W1   = (const float*)d_in[7];
    const float* b1   = (const float*)d_in[8];
    const float* W2   = (const float*)d_in[9];
    const float* b2   = (const float*)d_in[10];
    const float* g1   = (const float*)d_in[11];
    const float* be1  = (const float*)d_in[12];
    const float* g2   = (const float*)d_in[13];
    const float* be2  = (const float*)d_in[14];
    float* out = (float*)d_out;

    bf16 *xqh,*xql,*xkh,*xkl,*wqh,*wql,*wkh,*wkl,*wvh,*wvl,*woh,*wol,*w1h,*w1l,*w2h,*w2l;
    bf16 *qh,*ql,*kh,*kl,*vh,*vl,*oh,*ol,*lnh,*lnl,*hH,*hL;
    float *x1,*x2;
    cudaGetSymbolAddress((void**)&xqh, s_xq_h); cudaGetSymbolAddress((void**)&xql, s_xq_l);
    cudaGetSymbolAddress((void**)&xkh, s_xk_h); cudaGetSymbolAddress((void**)&xkl, s_xk_l);
    cudaGetSymbolAddress((void**)&wqh, s_wq_h); cudaGetSymbolAddress((void**)&wql, s_wq_l);
    cudaGetSymbolAddress((void**)&wkh, s_wk_h); cudaGetSymbolAddress((void**)&wkl, s_wk_l);
    cudaGetSymbolAddress((void**)&wvh, s_wv_h); cudaGetSymbolAddress((void**)&wvl, s_wv_l);
    cudaGetSymbolAddress((void**)&woh, s_wo_h); cudaGetSymbolAddress((void**)&wol, s_wo_l);
    cudaGetSymbolAddress((void**)&w1h, s_w1_h); cudaGetSymbolAddress((void**)&w1l, s_w1_l);
    cudaGetSymbolAddress((void**)&w2h, s_w2_h); cudaGetSymbolAddress((void**)&w2l, s_w2_l);
    cudaGetSymbolAddress((void**)&qh,  s_q_h);  cudaGetSymbolAddress((void**)&ql,  s_q_l);
    cudaGetSymbolAddress((void**)&kh,  s_k_h);  cudaGetSymbolAddress((void**)&kl,  s_k_l);
    cudaGetSymbolAddress((void**)&vh,  s_v_h);  cudaGetSymbolAddress((void**)&vl,  s_v_l);
    cudaGetSymbolAddress((void**)&oh,  s_o_h);  cudaGetSymbolAddress((void**)&ol,  s_o_l);
    cudaGetSymbolAddress((void**)&x1,  s_x1);
    cudaGetSymbolAddress((void**)&lnh, s_ln_h); cudaGetSymbolAddress((void**)&lnl, s_ln_l);
    cudaGetSymbolAddress((void**)&hH,  s_hh);   cudaGetSymbolAddress((void**)&hL,  s_hl);
    cudaGetSymbolAddress((void**)&x2,  s_x2);

    cudaFuncSetAttribute(gemm_mma<0,1>, cudaFuncAttributeMaxDynamicSharedMemorySize, SMEM_GEMM);
    cudaFuncSetAttribute(gemm_mma<1,0>, cudaFuncAttributeMaxDynamicSharedMemorySize, SMEM_GEMM);
    cudaFuncSetAttribute(gemm_mma<2,1>, cudaFuncAttributeMaxDynamicSharedMemorySize, SMEM_GEMM);
    cudaFuncSetAttribute(gemm_mma<3,0>, cudaFuncAttributeMaxDynamicSharedMemorySize, SMEM_GEMM);
    cudaFuncSetAttribute(flash_k,       cudaFuncAttributeMaxDynamicSharedMemorySize, SMEM_FLASH);

    // splits of inputs and weights
    split_k<<<MR*DM/1024, 256>>>(x_q,  xqh, xql);
    split_k<<<MR*DM/1024, 256>>>(x_kv, xkh, xkl);
    split_k<<<DM*DM/1024, 256>>>(Wq, wqh, wql);
    split_k<<<DM*DM/1024, 256>>>(Wk, wkh, wkl);
    split_k<<<DM*DM/1024, 256>>>(Wv, wvh, wvl);
    split_k<<<DM*DM/1024, 256>>>(Wo, woh, wol);
    split_k<<<FF*DM/1024, 256>>>(W1, w1h, w1l);
    split_k<<<DM*FF/1024, 256>>>(W2, w2h, w2l);

    // Q, K, V projections (all split out)
    {
        dim3 gr(DM/128, MR/128, 1);
        gemm_mma<0,1><<<gr, 256, SMEM_GEMM>>>(xqh, xql, wqh, wql, nullptr, qh, ql,
            DM, DM, DM, DM, 0, 0, 0, 1.0f, nullptr, 0, 0, nullptr);
        gemm_mma<0,1><<<gr, 256, SMEM_GEMM>>>(xkh, xkl, wkh, wkl, nullptr, kh, kl,
            DM, DM, DM, DM, 0, 0, 0, 1.0f, nullptr, 0, 0, nullptr);
        gemm_mma<0,1><<<gr, 256, SMEM_GEMM>>>(xkh, xkl, wvh, wvl, nullptr, vh, vl,
            DM, DM, DM, DM, 0, 0, 0, 1.0f, nullptr, 0, 0, nullptr);
    }

    // fused attention
    flash_k<<<dim3(SQ/128, NHD, BB), 256, SMEM_FLASH>>>(qh, ql, kh, kl, vh, vl, bias, oh, ol);

    // x1 = x_q + O @ Wo^T
    gemm_mma<1,0><<<dim3(DM/128, MR/128, 1), 256, SMEM_GEMM>>>(
        oh, ol, woh, wol, x1, nullptr, nullptr,
        DM, DM, DM, DM, 0, 0, 0, 1.0f, x_q, DM, 0, nullptr);

    ln_k<1><<<MR, 256>>>(x1, nullptr, lnh, lnl, g1, be1);

    // h = gelu(ln1 @ W1^T + b1)  (split out)
    gemm_mma<2,1><<<dim3(FF/128, MR/128, 1), 256, SMEM_GEMM>>>(
        lnh, lnl, w1h, w1l, nullptr, hH, hL,
        DM, DM, DM, FF, 0, 0, 0, 1.0f, nullptr, 0, 0, b1);

    // x2 = x1 + h @ W2^T + b2
    gemm_mma<3,0><<<dim3(DM/128, MR/128, 1), 256, SMEM_GEMM>>>(
        hH, hL, w2h, w2l, x2, nullptr, nullptr,
        FF, FF, FF, DM, 0, 0, 0, 1.0f, x1, DM, 0, b2);

    ln_k<0><<<MR, 256>>>(x2, out, nullptr, nullptr, g2, be2);
}

// round 7
// speedup vs baseline: 2.5294x; 1.0728x over previous
#include <cuda_runtime.h>
#include <cuda_bf16.h>
#include <cstdint>
#include <math.h>

typedef __nv_bfloat16 bf16;
typedef unsigned int u32;

#define BB 2
#define SQ 2048
#define DM 1024
#define NHD 16
#define FF 4096
#define MR (BB*SQ)

// ------------------- scratch (device globals) -------------------
__device__ bf16 s_xq_h[MR*DM], s_xq_l[MR*DM];
__device__ bf16 s_xk_h[MR*DM], s_xk_l[MR*DM];
__device__ bf16 s_wq_h[DM*DM], s_wq_l[DM*DM];
__device__ bf16 s_wk_h[DM*DM], s_wk_l[DM*DM];
__device__ bf16 s_wv_h[DM*DM], s_wv_l[DM*DM];
__device__ bf16 s_wo_h[DM*DM], s_wo_l[DM*DM];
__device__ bf16 s_w1_h[FF*DM], s_w1_l[FF*DM];
__device__ bf16 s_w2_h[DM*FF], s_w2_l[DM*FF];
__device__ bf16 s_q_h[MR*DM],  s_q_l[MR*DM];
__device__ bf16 s_k_h[MR*DM],  s_k_l[MR*DM];
__device__ bf16 s_v_h[MR*DM],  s_v_l[MR*DM];
__device__ bf16 s_o_h[MR*DM],  s_o_l[MR*DM];
__device__ float s_x1[MR*DM];
__device__ bf16 s_ln_h[MR*DM], s_ln_l[MR*DM];
__device__ bf16 s_hh[(size_t)MR*FF], s_hl[(size_t)MR*FF];
__device__ float s_x2[MR*DM];

// ------------------- helpers -------------------
__device__ __forceinline__ u32 smem_u32(const void* p) {
    return (u32)__cvta_generic_to_shared(p);
}
#define CP16(dst, src) \
    asm volatile("cp.async.cg.shared.global [%0], [%1], 16;" :: "r"(dst), "l"(src))
#define CP_COMMIT() asm volatile("cp.async.commit_group;" ::: "memory")
#define CP_WAIT1()  asm volatile("cp.async.wait_group 1;" ::: "memory")
#define CP_WAIT0()  asm volatile("cp.async.wait_group 0;" ::: "memory")

#define LDSM4(r0, r1, r2, r3, addr) \
    asm volatile("ldmatrix.sync.aligned.m8n8.x4.shared.b16 {%0,%1,%2,%3}, [%4];" \
        : "=r"(r0), "=r"(r1), "=r"(r2), "=r"(r3) : "r"(addr))
#define LDSM4T(r0, r1, r2, r3, addr) \
    asm volatile("ldmatrix.sync.aligned.m8n8.x4.trans.shared.b16 {%0,%1,%2,%3}, [%4];" \
        : "=r"(r0), "=r"(r1), "=r"(r2), "=r"(r3) : "r"(addr))

__device__ __forceinline__ void mma_bf16(float* c, const u32* a, const u32* b) {
    asm volatile("mma.sync.aligned.m16n8k16.row.col.f32.bf16.bf16.f32 "
        "{%0,%1,%2,%3}, {%4,%5,%6,%7}, {%8,%9}, {%0,%1,%2,%3};"
        : "+f"(c[0]), "+f"(c[1]), "+f"(c[2]), "+f"(c[3])
        : "r"(a[0]), "r"(a[1]), "r"(a[2]), "r"(a[3]), "r"(b[0]), "r"(b[1]));
}

__device__ __forceinline__ void split2(float v, bf16& h, bf16& l) {
    h = __float2bfloat16(v);
    l = __float2bfloat16(v - __bfloat162float(h));
}

// ------------------- HMMA GEMM -------------------
// C[m,n] = alpha * sum_k A[m,k]*B[n,k] (+ epilogue); A/B bf16 hi/lo splits (K-major).
// EPI: 0 none; 1 +addM; 2 +biasN then GELU; 3 +addM +biasN
// OUTM: 0 -> fp32 C; 1 -> split bf16 (Ch, Cl)
// BM=128, BN=128, BK=32. 128 threads = 4 warps (2Mx2N), warp tile 64x64.
// 2-stage cp.async pipeline, 80KB smem -> 2 CTAs/SM.
template<int EPI, int OUTM>
__global__ __launch_bounds__(128, 2)
void gemm_mma(const bf16* __restrict__ Ah, const bf16* __restrict__ Al,
              const bf16* __restrict__ Bh, const bf16* __restrict__ Bl,
              float* __restrict__ C, bf16* __restrict__ Ch, bf16* __restrict__ Cl,
              int K, int lda, int ldb, int ldc,
              long long sA, long long sB, long long sC,
              float alpha,
              const float* __restrict__ addM, int ldadd, long long sAdd,
              const float* __restrict__ biasN)
{
    constexpr u32 ROWB  = 80;
    constexpr u32 A_LO  = 128 * ROWB;      // 10240
    constexpr u32 B_OFF = 2 * 128 * ROWB;  // 20480
    constexpr u32 B_LO  = 128 * ROWB;
    constexpr u32 STG   = 4 * 128 * ROWB;  // 40960

    extern __shared__ char smem[];
    const u32 sbase = smem_u32(smem);
    const int tid = threadIdx.x, lane = tid & 31, wid = tid >> 5;
    const int wm = wid & 1, wn = wid >> 1;
    const long long z = blockIdx.z;

    Ah += z * sA;  Al += z * sA;
    Bh += z * sB;  Bl += z * sB;

    const int m0 = blockIdx.y * 128, n0 = blockIdx.x * 128;

    float acc[4][8][4];
    #pragma unroll
    for (int i = 0; i < 4; i++)
        #pragma unroll
        for (int j = 0; j < 8; j++)
            #pragma unroll
            for (int t = 0; t < 4; t++) acc[i][j][t] = 0.0f;

    auto load_chunk = [&](int ck, int st) {
        const int k0 = ck * 32;
        const u32 sa = sbase + (u32)st * STG;
        #pragma unroll
        for (int it = 0; it < 4; it++) {
            int a = tid + it * 128;            // 0..511
            int row = a >> 2, ch = a & 3;
            u32 dst = sa + (u32)row * ROWB + (u32)ch * 16;
            const size_t ga = (size_t)(m0 + row) * lda + k0 + ch * 8;
            const size_t gb = (size_t)(n0 + row) * ldb + k0 + ch * 8;
            CP16(dst,                Ah + ga);
            CP16(dst + A_LO,         Al + ga);
            CP16(dst + B_OFF,        Bh + gb);
            CP16(dst + B_OFF + B_LO, Bl + gb);
        }
    };

    auto compute = [&](int st) {
        const u32 ab  = sbase + (u32)st * STG;
        const u32 bb  = ab + B_OFF;
        const u32 rb  = (u32)((lane & 15) * ROWB);
        #pragma unroll
        for (int s16 = 0; s16 < 2; s16++) {
            const u32 coff = (u32)(s16 * 32 + (lane >> 4) * 16);
            u32 ah[4][4], al[4][4];
            #pragma unroll
            for (int mt = 0; mt < 4; mt++) {
                u32 ad = ab + (u32)((wm * 64 + mt * 16) * ROWB) + rb + coff;
                LDSM4(ah[mt][0], ah[mt][1], ah[mt][2], ah[mt][3], ad);
                LDSM4(al[mt][0], al[mt][1], al[mt][2], al[mt][3], ad + A_LO);
            }
            u32 bh[8][2], bl[8][2];
            #pragma unroll
            for (int np = 0; np < 4; np++) {
                u32 bd = bb + (u32)((wn * 64 + np * 16) * ROWB) + rb + coff;
                u32 t0, t1, t2, t3;
                LDSM4(t0, t1, t2, t3, bd);
                bh[2*np][0] = t0; bh[2*np+1][0] = t1; bh[2*np][1] = t2; bh[2*np+1][1] = t3;
                LDSM4(t0, t1, t2, t3, bd + B_LO);
                bl[2*np][0] = t0; bl[2*np+1][0] = t1; bl[2*np][1] = t2; bl[2*np+1][1] = t3;
            }
            #pragma unroll
            for (int mt = 0; mt < 4; mt++)
                #pragma unroll
                for (int nt = 0; nt < 8; nt++) {
                    mma_bf16(acc[mt][nt], ah[mt], bh[nt]);
                    mma_bf16(acc[mt][nt], ah[mt], bl[nt]);
                    mma_bf16(acc[mt][nt], al[mt], bh[nt]);
                }
        }
    };

    const int NC = K >> 5;
    load_chunk(0, 0); CP_COMMIT();
    for (int i = 0; i < NC; i++) {
        if (i + 1 < NC) { load_chunk(i + 1, (i + 1) & 1); CP_COMMIT(); CP_WAIT1(); }
        else            { CP_WAIT0(); }
        __syncthreads();
        compute(i & 1);
        __syncthreads();
    }

    // -------- epilogue --------
    auto proc2 = [&](int gm, int gn, float v0, float v1) {
        v0 *= alpha; v1 *= alpha;
        if (EPI == 1 || EPI == 3) {
            float2 ad = *(const float2*)(addM + z * sAdd + (size_t)gm * ldadd + gn);
            v0 += ad.x; v1 += ad.y;
        }
        if (EPI == 2 || EPI == 3) {
            float2 bn2 = *(const float2*)(biasN + gn);
            v0 += bn2.x; v1 += bn2.y;
        }
        if (EPI == 2) {
            v0 = 0.5f * v0 * (1.0f + erff(v0 * 0.70710678118654752f));
            v1 = 0.5f * v1 * (1.0f + erff(v1 * 0.70710678118654752f));
        }
        if (OUTM == 0) {
            *(float2*)(C + z * sC + (size_t)gm * ldc + gn) = make_float2(v0, v1);
        } else {
            bf16 h0, l0, h1, l1;
            split2(v0, h0, l0); split2(v1, h1, l1);
            u32 hp = (u32)__bfloat16_as_ushort(h0) | ((u32)__bfloat16_as_ushort(h1) << 16);
            u32 lp = (u32)__bfloat16_as_ushort(l0) | ((u32)__bfloat16_as_ushort(l1) << 16);
            *(u32*)(Ch + z * sC + (size_t)gm * ldc + gn) = hp;
            *(u32*)(Cl + z * sC + (size_t)gm * ldc + gn) = lp;
        }
    };

    const int r  = lane >> 2;
    const int c2 = (lane & 3) * 2;
    #pragma unroll
    for (int mt = 0; mt < 4; mt++) {
        #pragma unroll
        for (int nt = 0; nt < 8; nt++) {
            int gm = m0 + wm * 64 + mt * 16 + r;
            int gn = n0 + wn * 64 + nt * 8 + c2;
            proc2(gm,     gn, acc[mt][nt][0], acc[mt][nt][1]);
            proc2(gm + 8, gn, acc[mt][nt][2], acc[mt][nt][3]);
        }
    }
}

// ------------------- fused flash attention -------------------
__global__ __launch_bounds__(256, 1)
void flash_k(const bf16* __restrict__ qh, const bf16* __restrict__ ql,
             const bf16* __restrict__ kh, const bf16* __restrict__ kl,
             const bf16* __restrict__ vh, const bf16* __restrict__ vl,
             const float* __restrict__ bias,
             bf16* __restrict__ oh, bf16* __restrict__ ol)
{
    constexpr u32 ROWB = 144;
    constexpr u32 HKV  = 64 * ROWB;
    constexpr u32 STG  = 4 * HKV;

    extern __shared__ char smem[];
    const u32 sbase = smem_u32(smem);
    const int tid = threadIdx.x, lane = tid & 31, wid = tid >> 5;
    const int b = blockIdx.z, h = blockIdx.y, q0 = blockIdx.x * 128;

    const size_t qbase = ((size_t)b * SQ + q0) * DM + h * 64;
    const size_t kvbase = (size_t)b * SQ * DM + h * 64;
    const float* bptr = bias + ((size_t)(b * NHD + h)) * SQ * SQ;

    #pragma unroll
    for (int it = 0; it < 4; it++) {
        int idx = tid + it * 256;
        int row = idx >> 3, c8 = idx & 7;
        u32 dst = sbase + (u32)row * ROWB + (u32)c8 * 16;
        CP16(dst,            qh + qbase + (size_t)row * DM + c8 * 8);
        CP16(dst + 128*ROWB, ql + qbase + (size_t)row * DM + c8 * 8);
    }
    CP_COMMIT(); CP_WAIT0();
    __syncthreads();

    u32 qhf[4][4], qlf[4][4];
    {
        const u32 base = sbase + (u32)((wid * 16 + (lane & 15)) * ROWB);
        #pragma unroll
        for (int kq = 0; kq < 4; kq++) {
            u32 ad = base + (u32)(kq * 32 + (lane >> 4) * 16);
            LDSM4(qhf[kq][0], qhf[kq][1], qhf[kq][2], qhf[kq][3], ad);
            LDSM4(qlf[kq][0], qlf[kq][1], qlf[kq][2], qlf[kq][3], ad + 128*ROWB);
        }
    }
    __syncthreads();

    auto load_kv = [&](int ck, u32 st) {
        const int kv0 = ck * 64;
        #pragma unroll
        for (int it = 0; it < 2; it++) {
            int idx = tid + it * 256;
            int row = idx >> 3, c8 = idx & 7;
            size_t g = kvbase + (size_t)(kv0 + row) * DM + c8 * 8;
            u32 dst = st + (u32)row * ROWB + (u32)c8 * 16;
            CP16(dst,           kh + g);
            CP16(dst + HKV,     kl + g);
            CP16(dst + 2*HKV,   vh + g);
            CP16(dst + 3*HKV,   vl + g);
        }
    };

    float o[8][4];
    #pragma unroll
    for (int d = 0; d < 8; d++)
        #pragma unroll
        for (int t = 0; t < 4; t++) o[d][t] = 0.0f;
    float rm0 = -1e30f, rm1 = -1e30f, rs0 = 0.0f, rs1 = 0.0f;

    load_kv(0, sbase); CP_COMMIT();

    const u32 rbA = (u32)((lane & 15) * ROWB);
    const int g4  = lane >> 2, t4 = lane & 3;

    for (int ck = 0; ck < SQ / 64; ck++) {
        const u32 st = sbase + (u32)(ck & 1) * STG;
        if (ck + 1 < SQ / 64) { load_kv(ck + 1, sbase + (u32)((ck + 1) & 1) * STG); CP_COMMIT(); CP_WAIT1(); }
        else                  { CP_WAIT0(); }
        __syncthreads();

        float S[8][4];
        #pragma unroll
        for (int j = 0; j < 8; j++)
            #pragma unroll
            for (int t = 0; t < 4; t++) S[j][t] = 0.0f;

        #pragma unroll
        for (int kq = 0; kq < 4; kq++) {
            const u32 coff = (u32)(kq * 32 + (lane >> 4) * 16);
            #pragma unroll
            for (int jp = 0; jp < 4; jp++) {
                u32 kd = st + (u32)(jp * 16 * ROWB) + rbA + coff;
                u32 t0, t1, t2, t3;
                u32 bh[2][2], bl[2][2];
                LDSM4(t0, t1, t2, t3, kd);
                bh[0][0] = t0; bh[1][0] = t1; bh[0][1] = t2; bh[1][1] = t3;
                LDSM4(t0, t1, t2, t3, kd + HKV);
                bl[0][0] = t0; bl[1][0] = t1; bl[0][1] = t2; bl[1][1] = t3;
                #pragma unroll
                for (int u = 0; u < 2; u++) {
                    mma_bf16(S[2*jp+u], qhf[kq], bh[u]);
                    mma_bf16(S[2*jp+u], qhf[kq], bl[u]);
                    mma_bf16(S[2*jp+u], qlf[kq], bh[u]);
                }
            }
        }

        const int kv0 = ck * 64;
        const int row0 = q0 + wid * 16 + g4;
        #pragma unroll
        for (int j = 0; j < 8; j++) {
            const int col = kv0 + j * 8 + t4 * 2;
            float2 bz0 = *(const float2*)(bptr + (size_t)row0 * SQ + col);
            float2 bz1 = *(const float2*)(bptr + (size_t)(row0 + 8) * SQ + col);
            S[j][0] = S[j][0] * 0.125f + bz0.x;
            S[j][1] = S[j][1] * 0.125f + bz0.y;
            S[j][2] = S[j][2] * 0.125f + bz1.x;
            S[j][3] = S[j][3] * 0.125f + bz1.y;
        }

        float m0 = -1e30f, m1 = -1e30f;
        #pragma unroll
        for (int j = 0; j < 8; j++) {
            m0 = fmaxf(m0, fmaxf(S[j][0], S[j][1]));
            m1 = fmaxf(m1, fmaxf(S[j][2], S[j][3]));
        }
        m0 = fmaxf(m0, __shfl_xor_sync(0xffffffffu, m0, 1));
        m0 = fmaxf(m0, __shfl_xor_sync(0xffffffffu, m0, 2));
        m1 = fmaxf(m1, __shfl_xor_sync(0xffffffffu, m1, 1));
        m1 = fmaxf(m1, __shfl_xor_sync(0xffffffffu, m1, 2));
        const float nm0 = fmaxf(rm0, m0), nm1 = fmaxf(rm1, m1);
        const float f0 = __expf(rm0 - nm0), f1 = __expf(rm1 - nm1);
        float ls0 = 0.0f, ls1 = 0.0f;
        #pragma unroll
        for (int j = 0; j < 8; j++) {
            S[j][0] = __expf(S[j][0] - nm0); ls0 += S[j][0];
            S[j][1] = __expf(S[j][1] - nm0); ls0 += S[j][1];
            S[j][2] = __expf(S[j][2] - nm1); ls1 += S[j][2];
            S[j][3] = __expf(S[j][3] - nm1); ls1 += S[j][3];
        }
        rs0 = rs0 * f0 + ls0;
        rs1 = rs1 * f1 + ls1;
        rm0 = nm0; rm1 = nm1;
        #pragma unroll
        for (int d = 0; d < 8; d++) {
            o[d][0] *= f0; o[d][1] *= f0; o[d][2] *= f1; o[d][3] *= f1;
        }

        u32 pa[4][4], pb[4][4];
        #pragma unroll
        for (int kp = 0; kp < 4; kp++) {
            bf16 h00,l00,h01,l01,h10,l10,h11,l11,h20,l20,h21,l21,h30,l30,h31,l31;
            split2(S[2*kp][0],h00,l00);   split2(S[2*kp][1],h01,l01);
            split2(S[2*kp][2],h10,l10);   split2(S[2*kp][3],h11,l11);
            split2(S[2*kp+1][0],h20,l20); split2(S[2*kp+1][1],h21,l21);
            split2(S[2*kp+1][2],h30,l30); split2(S[2*kp+1][3],h31,l31);
            pa[kp][0] = (u32)__bfloat16_as_ushort(h00) | ((u32)__bfloat16_as_ushort(h01) << 16);
            pa[kp][1] = (u32)__bfloat16_as_ushort(h10) | ((u32)__bfloat16_as_ushort(h11) << 16);
            pa[kp][2] = (u32)__bfloat16_as_ushort(h20) | ((u32)__bfloat16_as_ushort(h21) << 16);
            pa[kp][3] = (u32)__bfloat16_as_ushort(h30) | ((u32)__bfloat16_as_ushort(h31) << 16);
            pb[kp][0] = (u32)__bfloat16_as_ushort(l00) | ((u32)__bfloat16_as_ushort(l01) << 16);
            pb[kp][1] = (u32)__bfloat16_as_ushort(l10) | ((u32)__bfloat16_as_ushort(l11) << 16);
            pb[kp][2] = (u32)__bfloat16_as_ushort(l20) | ((u32)__bfloat16_as_ushort(l21) << 16);
            pb[kp][3] = (u32)__bfloat16_as_ushort(l30) | ((u32)__bfloat16_as_ushort(l31) << 16);
        }

        const u32 vbase = st + 2 * HKV;
        const u32 vrow  = (u32)((lane & 7) + 8 * ((lane >> 3) & 1));
        const u32 vcolb = (u32)((lane >> 4) * 16);
        #pragma unroll
        for (int kp = 0; kp < 4; kp++) {
            #pragma unroll
            for (int dp = 0; dp < 4; dp++) {
                u32 vd = vbase + (u32)((kp * 16 + vrow) * ROWB) + (u32)(dp * 32) + vcolb;
                u32 r0, r1, r2, r3;
                u32 vhf[2][2], vlf[2][2];
                LDSM4T(r0, r1, r2, r3, vd);
                vhf[0][0] = r0; vhf[0][1] = r1; vhf[1][0] = r2; vhf[1][1] = r3;
                LDSM4T(r0, r1, r2, r3, vd + HKV);
                vlf[0][0] = r0; vlf[0][1] = r1; vlf[1][0] = r2; vlf[1][1] = r3;
                #pragma unroll
                for (int u = 0; u < 2; u++) {
                    mma_bf16(o[2*dp+u], pa[kp], vhf[u]);
                    mma_bf16(o[2*dp+u], pb[kp], vhf[u]);
                    mma_bf16(o[2*dp+u], pa[kp], vlf[u]);
                }
            }
        }
        __syncthreads();
    }

    rs0 += __shfl_xor_sync(0xffffffffu, rs0, 1);
    rs0 += __shfl_xor_sync(0xffffffffu, rs0, 2);
    rs1 += __shfl_xor_sync(0xffffffffu, rs1, 1);
    rs1 += __shfl_xor_sync(0xffffffffu, rs1, 2);
    const float i0 = 1.0f / rs0, i1 = 1.0f / rs1;
    const int row0 = q0 + wid * 16 + g4;
    #pragma unroll
    for (int d = 0; d < 8; d++) {
        const int col = h * 64 + d * 8 + t4 * 2;
        bf16 h0, l0, h1, l1;
        split2(o[d][0] * i0, h0, l0); split2(o[d][1] * i0, h1, l1);
        *(u32*)(oh + ((size_t)b * SQ + row0) * DM + col) =
            (u32)__bfloat16_as_ushort(h0) | ((u32)__bfloat16_as_ushort(h1) << 16);
        *(u32*)(ol + ((size_t)b * SQ + row0) * DM + col) =
            (u32)__bfloat16_as_ushort(l0) | ((u32)__bfloat16_as_ushort(l1) << 16);
        split2(o[d][2] * i1, h0, l0); split2(o[d][3] * i1, h1, l1);
        *(u32*)(oh + ((size_t)b * SQ + row0 + 8) * DM + col) =
            (u32)__bfloat16_as_ushort(h0) | ((u32)__bfloat16_as_ushort(h1) << 16);
        *(u32*)(ol + ((size_t)b * SQ + row0 + 8) * DM + col) =
            (u32)__bfloat16_as_ushort(l0) | ((u32)__bfloat16_as_ushort(l1) << 16);
    }
}

// ------------------- merged split fp32 -> (hi, lo) bf16 -------------------
struct SplitTab {
    const float* x[8];
    bf16* h[8];
    bf16* l[8];
    int endblk[8];
};

__global__ __launch_bounds__(256)
void splitall_k(SplitTab t)
{
    int bk = blockIdx.x;
    int r = 0;
    #pragma unroll
    for (int j = 0; j < 8; j++) if (bk >= t.endblk[j]) r = j + 1;
    int start = r ? t.endblk[r - 1] : 0;
    size_t i = (size_t)(bk - start) * 256 + threadIdx.x;
    float4 v = ((const float4*)t.x[r])[i];
    bf16 h0,l0,h1,l1,h2,l2,h3,l3;
    split2(v.x,h0,l0); split2(v.y,h1,l1); split2(v.z,h2,l2); split2(v.w,h3,l3);
    uint2 hp = make_uint2((u32)__bfloat16_as_ushort(h0) | ((u32)__bfloat16_as_ushort(h1)<<16),
                          (u32)__bfloat16_as_ushort(h2) | ((u32)__bfloat16_as_ushort(h3)<<16));
    uint2 lp = make_uint2((u32)__bfloat16_as_ushort(l0) | ((u32)__bfloat16_as_ushort(l1)<<16),
                          (u32)__bfloat16_as_ushort(l2) | ((u32)__bfloat16_as_ushort(l3)<<16));
    ((uint2*)t.h[r])[i] = hp;
    ((uint2*)t.l[r])[i] = lp;
}

// ------------------- LayerNorm rows of 1024 -------------------
template<int OUTM>
__global__ __launch_bounds__(256)
void ln_k(const float* __restrict__ x, float* __restrict__ y,
          bf16* __restrict__ yh, bf16* __restrict__ yl,
          const float* __restrict__ gg, const float* __restrict__ bb)
{
    const float* p = x + (size_t)blockIdx.x * DM;
    const int tid = threadIdx.x, lane = tid & 31, warp = tid >> 5;
    __shared__ float r1[8], r2[8];

    float4 v4 = ((const float4*)p)[tid];
    float v[4] = {v4.x, v4.y, v4.z, v4.w};
    float sm = v[0]+v[1]+v[2]+v[3];
    float s2 = v[0]*v[0]+v[1]*v[1]+v[2]*v[2]+v[3]*v[3];
    #pragma unroll
    for (int o = 16; o; o >>= 1) {
        sm += __shfl_xor_sync(0xffffffffu, sm, o);
        s2 += __shfl_xor_sync(0xffffffffu, s2, o);
    }
    if (!lane) { r1[warp] = sm; r2[warp] = s2; }
    __syncthreads();
    sm = 0.0f; s2 = 0.0f;
    #pragma unroll
    for (int i = 0; i < 8; i++) { sm += r1[i]; s2 += r2[i]; }
    const float mean = sm * (1.0f / DM);
    const float var  = s2 * (1.0f / DM) - mean * mean;
    const float inv  = rsqrtf(var + 1e-5f);

    float4 g4 = ((const float4*)gg)[tid];
    float4 b4 = ((const float4*)bb)[tid];
    float o0 = (v[0]-mean)*inv*g4.x + b4.x;
    float o1 = (v[1]-mean)*inv*g4.y + b4.y;
    float o2 = (v[2]-mean)*inv*g4.z + b4.z;
    float o3 = (v[3]-mean)*inv*g4.w + b4.w;
    if (OUTM == 0) {
        ((float4*)(y + (size_t)blockIdx.x * DM))[tid] = make_float4(o0,o1,o2,o3);
    } else {
        bf16 h0,l0,h1,l1,h2,l2,h3,l3;
        split2(o0,h0,l0); split2(o1,h1,l1); split2(o2,h2,l2); split2(o3,h3,l3);
        uint2 hp = make_uint2((u32)__bfloat16_as_ushort(h0) | ((u32)__bfloat16_as_ushort(h1)<<16),
                              (u32)__bfloat16_as_ushort(h2) | ((u32)__bfloat16_as_ushort(h3)<<16));
        uint2 lp = make_uint2((u32)__bfloat16_as_ushort(l0) | ((u32)__bfloat16_as_ushort(l1)<<16),
                              (u32)__bfloat16_as_ushort(l2) | ((u32)__bfloat16_as_ushort(l3)<<16));
        ((uint2*)(yh + (size_t)blockIdx.x * DM))[tid] = hp;
        ((uint2*)(yl + (size_t)blockIdx.x * DM))[tid] = lp;
    }
}

// ------------------- launch -------------------
#define SMEM_GEMM (2 * 4 * 128 * 80)    // 81920
#define SMEM_FLASH (2 * 4 * 64 * 144)   // 73728

extern "C" void kernel_launch(void* const* d_in, const int* in_sizes, int n_in,
                              void* d_out, int out_size)
{
    const float* x_q  = (const float*)d_in[0];
    const float* x_kv = (const float*)d_in[1];
    const float* bias = (const float*)d_in[2];
    const float* Wq   = (const float*)d_in[3];
    const float* Wk   = (const float*)d_in[4];
    const float* Wv   = (const float*)d_in[5];
    const float* Wo   = (const float*)d_in[6];
    const float* W1   = (const float*)d_in[7];
    const float* b1   = (const float*)d_in[8];
    const float* W2   = (const float*)d_in[9];
    const float* b2   = (const float*)d_in[10];
    const float* g1   = (const float*)d_in[11];
    const float* be1  = (const float*)d_in[12];
    const float* g2   = (const float*)d_in[13];
    const float* be2  = (const float*)d_in[14];
    float* out = (float*)d_out;

    bf16 *xqh,*xql,*xkh,*xkl,*wqh,*wql,*wkh,*wkl,*wvh,*wvl,*woh,*wol,*w1h,*w1l,*w2h,*w2l;
    bf16 *qh,*ql,*kh,*kl,*vh,*vl,*oh,*ol,*lnh,*lnl,*hH,*hL;
    float *x1,*x2;
    cudaGetSymbolAddress((void**)&xqh, s_xq_h); cudaGetSymbolAddress((void**)&xql, s_xq_l);
    cudaGetSymbolAddress((void**)&xkh, s_xk_h); cudaGetSymbolAddress((void**)&xkl, s_xk_l);
    cudaGetSymbolAddress((void**)&wqh, s_wq_h); cudaGetSymbolAddress((void**)&wql, s_wq_l);
    cudaGetSymbolAddress((void**)&wkh, s_wk_h); cudaGetSymbolAddress((void**)&wkl, s_wk_l);
    cudaGetSymbolAddress((void**)&wvh, s_wv_h); cudaGetSymbolAddress((void**)&wvl, s_wv_l);
    cudaGetSymbolAddress((void**)&woh, s_wo_h); cudaGetSymbolAddress((void**)&wol, s_wo_l);
    cudaGetSymbolAddress((void**)&w1h, s_w1_h); cudaGetSymbolAddress((void**)&w1l, s_w1_l);
    cudaGetSymbolAddress((void**)&w2h, s_w2_h); cudaGetSymbolAddress((void**)&w2l, s_w2_l);
    cudaGetSymbolAddress((void**)&qh,  s_q_h);  cudaGetSymbolAddress((void**)&ql,  s_q_l);
    cudaGetSymbolAddress((void**)&kh,  s_k_h);  cudaGetSymbolAddress((void**)&kl,  s_k_l);
    cudaGetSymbolAddress((void**)&vh,  s_v_h);  cudaGetSymbolAddress((void**)&vl,  s_v_l);
    cudaGetSymbolAddress((void**)&oh,  s_o_h);  cudaGetSymbolAddress((void**)&ol,  s_o_l);
    cudaGetSymbolAddress((void**)&x1,  s_x1);
    cudaGetSymbolAddress((void**)&lnh, s_ln_h); cudaGetSymbolAddress((void**)&lnl, s_ln_l);
    cudaGetSymbolAddress((void**)&hH,  s_hh);   cudaGetSymbolAddress((void**)&hL,  s_hl);
    cudaGetSymbolAddress((void**)&x2,  s_x2);

    cudaFuncSetAttribute(gemm_mma<0,1>, cudaFuncAttributeMaxDynamicSharedMemorySize, SMEM_GEMM);
    cudaFuncSetAttribute(gemm_mma<1,0>, cudaFuncAttributeMaxDynamicSharedMemorySize, SMEM_GEMM);
    cudaFuncSetAttribute(gemm_mma<2,1>, cudaFuncAttributeMaxDynamicSharedMemorySize, SMEM_GEMM);
    cudaFuncSetAttribute(gemm_mma<3,0>, cudaFuncAttributeMaxDynamicSharedMemorySize, SMEM_GEMM);
    cudaFuncSetAttribute(flash_k,       cudaFuncAttributeMaxDynamicSharedMemorySize, SMEM_FLASH);

    // one merged split launch for all 8 fp32->bf16 hi/lo conversions
    {
        SplitTab t;
        t.x[0]=x_q;  t.h[0]=xqh; t.l[0]=xql;
        t.x[1]=x_kv; t.h[1]=xkh; t.l[1]=xkl;
        t.x[2]=Wq;   t.h[2]=wqh; t.l[2]=wql;
        t.x[3]=Wk;   t.h[3]=wkh; t.l[3]=wkl;
        t.x[4]=Wv;   t.h[4]=wvh; t.l[4]=wvl;
        t.x[5]=Wo;   t.h[5]=woh; t.l[5]=wol;
        t.x[6]=W1;   t.h[6]=w1h; t.l[6]=w1l;
        t.x[7]=W2;   t.h[7]=w2h; t.l[7]=w2l;
        int blks[8] = {MR*DM/1024, MR*DM/1024, DM*DM/1024, DM*DM/1024,
                       DM*DM/1024, DM*DM/1024, FF*DM/1024, DM*FF/1024};
        int acc_ = 0;
        for (int j = 0; j < 8; j++) { acc_ += blks[j]; t.endblk[j] = acc_; }
        splitall_k<<<acc_, 256>>>(t);
    }

    // Q, K, V projections (all split out)
    {
        dim3 gr(DM/128, MR/128, 1);
        gemm_mma<0,1><<<gr, 128, SMEM_GEMM>>>(xqh, xql, wqh, wql, nullptr, qh, ql,
            DM, DM, DM, DM, 0, 0, 0, 1.0f, nullptr, 0, 0, nullptr);
        gemm_mma<0,1><<<gr, 128, SMEM_GEMM>>>(xkh, xkl, wkh, wkl, nullptr, kh, kl,
            DM, DM, DM, DM, 0, 0, 0, 1.0f, nullptr, 0, 0, nullptr);
        gemm_mma<0,1><<<gr, 128, SMEM_GEMM>>>(xkh, xkl, wvh, wvl, nullptr, vh, vl,
            DM, DM, DM, DM, 0, 0, 0, 1.0f, nullptr, 0, 0, nullptr);
    }

    // fused attention
    flash_k<<<dim3(SQ/128, NHD, BB), 256, SMEM_FLASH>>>(qh, ql, kh, kl, vh, vl, bias, oh, ol);

    // x1 = x_q + O @ Wo^T
    gemm_mma<1,0><<<dim3(DM/128, MR/128, 1), 128, SMEM_GEMM>>>(
        oh, ol, woh, wol, x1, nullptr, nullptr,
        DM, DM, DM, DM, 0, 0, 0, 1.0f, x_q, DM, 0, nullptr);

    ln_k<1><<<MR, 256>>>(x1, nullptr, lnh, lnl, g1, be1);

    // h = gelu(ln1 @ W1^T + b1)  (split out)
    gemm_mma<2,1><<<dim3(FF/128, MR/128, 1), 128, SMEM_GEMM>>>(
        lnh, lnl, w1h, w1l, nullptr, hH, hL,
        DM, DM, DM, FF, 0, 0, 0, 1.0f, nullptr, 0, 0, b1);

    // x2 = x1 + h @ W2^T + b2
    gemm_mma<3,0><<<dim3(DM/128, MR/128, 1), 128, SMEM_GEMM>>>(
        hH, hL, w2h, w2l, x2, nullptr, nullptr,
        FF, FF, FF, DM, 0, 0, 0, 1.0f, x1, DM, 0, b2);

    ln_k<0><<<MR, 256>>>(x2, out, nullptr, nullptr, g2, be2);
}

// round 8
// speedup vs baseline: 2.5801x; 1.0200x over previous
#include <cuda_runtime.h>
#include <cuda_bf16.h>
#include <cstdint>
#include <math.h>

typedef __nv_bfloat16 bf16;
typedef unsigned int u32;

#define BB 2
#define SQ 2048
#define DM 1024
#define NHD 16
#define FF 4096
#define MR (BB*SQ)

// ------------------- scratch (device globals) -------------------
__device__ bf16 s_xq_h[MR*DM], s_xq_l[MR*DM];
__device__ bf16 s_xk_h[MR*DM], s_xk_l[MR*DM];
__device__ bf16 s_wq_h[DM*DM], s_wq_l[DM*DM];
__device__ bf16 s_wk_h[DM*DM], s_wk_l[DM*DM];
__device__ bf16 s_wv_h[DM*DM], s_wv_l[DM*DM];
__device__ bf16 s_wo_h[DM*DM], s_wo_l[DM*DM];
__device__ bf16 s_w1_h[FF*DM], s_w1_l[FF*DM];
__device__ bf16 s_w2_h[DM*FF], s_w2_l[DM*FF];
__device__ bf16 s_q_h[MR*DM],  s_q_l[MR*DM];
__device__ bf16 s_k_h[MR*DM],  s_k_l[MR*DM];
__device__ bf16 s_v_h[MR*DM],  s_v_l[MR*DM];
__device__ bf16 s_o_h[MR*DM],  s_o_l[MR*DM];
__device__ float s_x1[MR*DM];
__device__ bf16 s_ln_h[MR*DM], s_ln_l[MR*DM];
__device__ bf16 s_hh[(size_t)MR*FF], s_hl[(size_t)MR*FF];
__device__ float s_x2[MR*DM];

// ------------------- helpers -------------------
__device__ __forceinline__ u32 smem_u32(const void* p) {
    return (u32)__cvta_generic_to_shared(p);
}
#define CP16(dst, src) \
    asm volatile("cp.async.cg.shared.global [%0], [%1], 16;" :: "r"(dst), "l"(src))
#define CP_COMMIT() asm volatile("cp.async.commit_group;" ::: "memory")
#define CP_WAIT0()  asm volatile("cp.async.wait_group 0;" ::: "memory")

#define LDSM4(r0, r1, r2, r3, addr) \
    asm volatile("ldmatrix.sync.aligned.m8n8.x4.shared.b16 {%0,%1,%2,%3}, [%4];" \
        : "=r"(r0), "=r"(r1), "=r"(r2), "=r"(r3) : "r"(addr))
#define LDSM4T(r0, r1, r2, r3, addr) \
    asm volatile("ldmatrix.sync.aligned.m8n8.x4.trans.shared.b16 {%0,%1,%2,%3}, [%4];" \
        : "=r"(r0), "=r"(r1), "=r"(r2), "=r"(r3) : "r"(addr))

__device__ __forceinline__ void mma_bf16(float* c, const u32* a, const u32* b) {
    asm volatile("mma.sync.aligned.m16n8k16.row.col.f32.bf16.bf16.f32 "
        "{%0,%1,%2,%3}, {%4,%5,%6,%7}, {%8,%9}, {%0,%1,%2,%3};"
        : "+f"(c[0]), "+f"(c[1]), "+f"(c[2]), "+f"(c[3])
        : "r"(a[0]), "r"(a[1]), "r"(a[2]), "r"(a[3]), "r"(b[0]), "r"(b[1]));
}

__device__ __forceinline__ void split2(float v, bf16& h, bf16& l) {
    h = __float2bfloat16(v);
    l = __float2bfloat16(v - __bfloat162float(h));
}

// ------------------- HMMA GEMM -------------------
// C[m,n] = alpha * sum_k A[m,k]*B[n,k] (+ epilogue); A/B bf16 hi/lo splits (K-major).
// EPI: 0 none; 1 +addM; 2 +biasN then GELU; 3 +addM +biasN
// OUTM: 0 -> fp32 C; 1 -> split bf16 (Ch, Cl)
// BM=128, BN=128, BK=32. 128 threads = 4 warps (2Mx2N), warp tile 64x64.
// 2-stage cp.async, single sync per chunk, A-frags streamed to cap registers.
template<int EPI, int OUTM>
__global__ __launch_bounds__(128, 2)
void gemm_mma(const bf16* __restrict__ Ah, const bf16* __restrict__ Al,
              const bf16* __restrict__ Bh, const bf16* __restrict__ Bl,
              float* __restrict__ C, bf16* __restrict__ Ch, bf16* __restrict__ Cl,
              int K, int lda, int ldb, int ldc,
              long long sA, long long sB, long long sC,
              float alpha,
              const float* __restrict__ addM, int ldadd, long long sAdd,
              const float* __restrict__ biasN)
{
    constexpr u32 ROWB  = 80;
    constexpr u32 A_LO  = 128 * ROWB;      // 10240
    constexpr u32 B_OFF = 2 * 128 * ROWB;  // 20480
    constexpr u32 B_LO  = 128 * ROWB;
    constexpr u32 STG   = 4 * 128 * ROWB;  // 40960

    extern __shared__ char smem[];
    const u32 sbase = smem_u32(smem);
    const int tid = threadIdx.x, lane = tid & 31, wid = tid >> 5;
    const int wm = wid & 1, wn = wid >> 1;
    const long long z = blockIdx.z;

    Ah += z * sA;  Al += z * sA;
    Bh += z * sB;  Bl += z * sB;

    const int m0 = blockIdx.y * 128, n0 = blockIdx.x * 128;

    float acc[4][8][4];
    #pragma unroll
    for (int i = 0; i < 4; i++)
        #pragma unroll
        for (int j = 0; j < 8; j++)
            #pragma unroll
            for (int t = 0; t < 4; t++) acc[i][j][t] = 0.0f;

    auto load_chunk = [&](int ck, int st) {
        const int k0 = ck * 32;
        const u32 sa = sbase + (u32)st * STG;
        #pragma unroll
        for (int it = 0; it < 4; it++) {
            int a = tid + it * 128;            // 0..511
            int row = a >> 2, ch = a & 3;
            u32 dst = sa + (u32)row * ROWB + (u32)ch * 16;
            const size_t ga = (size_t)(m0 + row) * lda + k0 + ch * 8;
            const size_t gb = (size_t)(n0 + row) * ldb + k0 + ch * 8;
            CP16(dst,                Ah + ga);
            CP16(dst + A_LO,         Al + ga);
            CP16(dst + B_OFF,        Bh + gb);
            CP16(dst + B_OFF + B_LO, Bl + gb);
        }
    };

    auto compute = [&](int st) {
        const u32 ab  = sbase + (u32)st * STG;
        const u32 bb  = ab + B_OFF;
        const u32 rb  = (u32)((lane & 15) * ROWB);
        #pragma unroll
        for (int s16 = 0; s16 < 2; s16++) {
            const u32 coff = (u32)(s16 * 32 + (lane >> 4) * 16);
            // hold all B frags (32 regs), stream A frags per mt (8 regs)
            u32 bh[8][2], bl[8][2];
            #pragma unroll
            for (int np = 0; np < 4; np++) {
                u32 bd = bb + (u32)((wn * 64 + np * 16) * ROWB) + rb + coff;
                u32 t0, t1, t2, t3;
                LDSM4(t0, t1, t2, t3, bd);
                bh[2*np][0] = t0; bh[2*np+1][0] = t1; bh[2*np][1] = t2; bh[2*np+1][1] = t3;
                LDSM4(t0, t1, t2, t3, bd + B_LO);
                bl[2*np][0] = t0; bl[2*np+1][0] = t1; bl[2*np][1] = t2; bl[2*np+1][1] = t3;
            }
            #pragma unroll
            for (int mt = 0; mt < 4; mt++) {
                u32 ah[4], al[4];
                u32 ad = ab + (u32)((wm * 64 + mt * 16) * ROWB) + rb + coff;
                LDSM4(ah[0], ah[1], ah[2], ah[3], ad);
                LDSM4(al[0], al[1], al[2], al[3], ad + A_LO);
                #pragma unroll
                for (int nt = 0; nt < 8; nt++) {
                    mma_bf16(acc[mt][nt], ah, bh[nt]);
                    mma_bf16(acc[mt][nt], ah, bl[nt]);
                    mma_bf16(acc[mt][nt], al, bh[nt]);
                }
            }
        }
    };

    const int NC = K >> 5;
    load_chunk(0, 0); CP_COMMIT();
    for (int i = 0; i < NC; i++) {
        CP_WAIT0();
        __syncthreads();
        if (i + 1 < NC) { load_chunk(i + 1, (i + 1) & 1); CP_COMMIT(); }
        compute(i & 1);
    }

    // -------- epilogue --------
    auto proc2 = [&](int gm, int gn, float v0, float v1) {
        v0 *= alpha; v1 *= alpha;
        if (EPI == 1 || EPI == 3) {
            float2 ad = *(const float2*)(addM + z * sAdd + (size_t)gm * ldadd + gn);
            v0 += ad.x; v1 += ad.y;
        }
        if (EPI == 2 || EPI == 3) {
            float2 bn2 = *(const float2*)(biasN + gn);
            v0 += bn2.x; v1 += bn2.y;
        }
        if (EPI == 2) {
            v0 = 0.5f * v0 * (1.0f + erff(v0 * 0.70710678118654752f));
            v1 = 0.5f * v1 * (1.0f + erff(v1 * 0.70710678118654752f));
        }
        if (OUTM == 0) {
            *(float2*)(C + z * sC + (size_t)gm * ldc + gn) = make_float2(v0, v1);
        } else {
            bf16 h0, l0, h1, l1;
            split2(v0, h0, l0); split2(v1, h1, l1);
            u32 hp = (u32)__bfloat16_as_ushort(h0) | ((u32)__bfloat16_as_ushort(h1) << 16);
            u32 lp = (u32)__bfloat16_as_ushort(l0) | ((u32)__bfloat16_as_ushort(l1) << 16);
            *(u32*)(Ch + z * sC + (size_t)gm * ldc + gn) = hp;
            *(u32*)(Cl + z * sC + (size_t)gm * ldc + gn) = lp;
        }
    };

    const int r  = lane >> 2;
    const int c2 = (lane & 3) * 2;
    #pragma unroll
    for (int mt = 0; mt < 4; mt++) {
        #pragma unroll
        for (int nt = 0; nt < 8; nt++) {
            int gm = m0 + wm * 64 + mt * 16 + r;
            int gn = n0 + wn * 64 + nt * 8 + c2;
            proc2(gm,     gn, acc[mt][nt][0], acc[mt][nt][1]);
            proc2(gm + 8, gn, acc[mt][nt][2], acc[mt][nt][3]);
        }
    }
}

// ------------------- fused flash attention -------------------
__global__ __launch_bounds__(256, 1)
void flash_k(const bf16* __restrict__ qh, const bf16* __restrict__ ql,
             const bf16* __restrict__ kh, const bf16* __restrict__ kl,
             const bf16* __restrict__ vh, const bf16* __restrict__ vl,
             const float* __restrict__ bias,
             bf16* __restrict__ oh, bf16* __restrict__ ol)
{
    constexpr u32 ROWB = 144;
    constexpr u32 HKV  = 64 * ROWB;
    constexpr u32 STG  = 4 * HKV;

    extern __shared__ char smem[];
    const u32 sbase = smem_u32(smem);
    const int tid = threadIdx.x, lane = tid & 31, wid = tid >> 5;
    const int b = blockIdx.z, h = blockIdx.y, q0 = blockIdx.x * 128;

    const size_t qbase = ((size_t)b * SQ + q0) * DM + h * 64;
    const size_t kvbase = (size_t)b * SQ * DM + h * 64;
    const float* bptr = bias + ((size_t)(b * NHD + h)) * SQ * SQ;

    #pragma unroll
    for (int it = 0; it < 4; it++) {
        int idx = tid + it * 256;
        int row = idx >> 3, c8 = idx & 7;
        u32 dst = sbase + (u32)row * ROWB + (u32)c8 * 16;
        CP16(dst,            qh + qbase + (size_t)row * DM + c8 * 8);
        CP16(dst + 128*ROWB, ql + qbase + (size_t)row * DM + c8 * 8);
    }
    CP_COMMIT(); CP_WAIT0();
    __syncthreads();

    u32 qhf[4][4], qlf[4][4];
    {
        const u32 base = sbase + (u32)((wid * 16 + (lane & 15)) * ROWB);
        #pragma unroll
        for (int kq = 0; kq < 4; kq++) {
            u32 ad = base + (u32)(kq * 32 + (lane >> 4) * 16);
            LDSM4(qhf[kq][0], qhf[kq][1], qhf[kq][2], qhf[kq][3], ad);
            LDSM4(qlf[kq][0], qlf[kq][1], qlf[kq][2], qlf[kq][3], ad + 128*ROWB);
        }
    }
    __syncthreads();

    auto load_kv = [&](int ck, u32 st) {
        const int kv0 = ck * 64;
        #pragma unroll
        for (int it = 0; it < 2; it++) {
            int idx = tid + it * 256;
            int row = idx >> 3, c8 = idx & 7;
            size_t g = kvbase + (size_t)(kv0 + row) * DM + c8 * 8;
            u32 dst = st + (u32)row * ROWB + (u32)c8 * 16;
            CP16(dst,           kh + g);
            CP16(dst + HKV,     kl + g);
            CP16(dst + 2*HKV,   vh + g);
            CP16(dst + 3*HKV,   vl + g);
        }
    };

    float o[8][4];
    #pragma unroll
    for (int d = 0; d < 8; d++)
        #pragma unroll
        for (int t = 0; t < 4; t++) o[d][t] = 0.0f;
    float rm0 = -1e30f, rm1 = -1e30f, rs0 = 0.0f, rs1 = 0.0f;

    load_kv(0, sbase); CP_COMMIT();

    const u32 rbA = (u32)((lane & 15) * ROWB);
    const int g4  = lane >> 2, t4 = lane & 3;

    for (int ck = 0; ck < SQ / 64; ck++) {
        const u32 st = sbase + (u32)(ck & 1) * STG;
        CP_WAIT0();
        __syncthreads();
        if (ck + 1 < SQ / 64) { load_kv(ck + 1, sbase + (u32)((ck + 1) & 1) * STG); CP_COMMIT(); }

        float S[8][4];
        #pragma unroll
        for (int j = 0; j < 8; j++)
            #pragma unroll
            for (int t = 0; t < 4; t++) S[j][t] = 0.0f;

        #pragma unroll
        for (int kq = 0; kq < 4; kq++) {
            const u32 coff = (u32)(kq * 32 + (lane >> 4) * 16);
            #pragma unroll
            for (int jp = 0; jp < 4; jp++) {
                u32 kd = st + (u32)(jp * 16 * ROWB) + rbA + coff;
                u32 t0, t1, t2, t3;
                u32 bh[2][2], bl[2][2];
                LDSM4(t0, t1, t2, t3, kd);
                bh[0][0] = t0; bh[1][0] = t1; bh[0][1] = t2; bh[1][1] = t3;
                LDSM4(t0, t1, t2, t3, kd + HKV);
                bl[0][0] = t0; bl[1][0] = t1; bl[0][1] = t2; bl[1][1] = t3;
                #pragma unroll
                for (int u = 0; u < 2; u++) {
                    mma_bf16(S[2*jp+u], qhf[kq], bh[u]);
                    mma_bf16(S[2*jp+u], qhf[kq], bl[u]);
                    mma_bf16(S[2*jp+u], qlf[kq], bh[u]);
                }
            }
        }

        const int kv0 = ck * 64;
        const int row0 = q0 + wid * 16 + g4;
        #pragma unroll
        for (int j = 0; j < 8; j++) {
            const int col = kv0 + j * 8 + t4 * 2;
            float2 bz0 = *(const float2*)(bptr + (size_t)row0 * SQ + col);
            float2 bz1 = *(const float2*)(bptr + (size_t)(row0 + 8) * SQ + col);
            S[j][0] = S[j][0] * 0.125f + bz0.x;
            S[j][1] = S[j][1] * 0.125f + bz0.y;
            S[j][2] = S[j][2] * 0.125f + bz1.x;
            S[j][3] = S[j][3] * 0.125f + bz1.y;
        }

        float m0 = -1e30f, m1 = -1e30f;
        #pragma unroll
        for (int j = 0; j < 8; j++) {
            m0 = fmaxf(m0, fmaxf(S[j][0], S[j][1]));
            m1 = fmaxf(m1, fmaxf(S[j][2], S[j][3]));
        }
        m0 = fmaxf(m0, __shfl_xor_sync(0xffffffffu, m0, 1));
        m0 = fmaxf(m0, __shfl_xor_sync(0xffffffffu, m0, 2));
        m1 = fmaxf(m1, __shfl_xor_sync(0xffffffffu, m1, 1));
        m1 = fmaxf(m1, __shfl_xor_sync(0xffffffffu, m1, 2));
        const float nm0 = fmaxf(rm0, m0), nm1 = fmaxf(rm1, m1);
        const float f0 = __expf(rm0 - nm0), f1 = __expf(rm1 - nm1);
        float ls0 = 0.0f, ls1 = 0.0f;
        #pragma unroll
        for (int j = 0; j < 8; j++) {
            S[j][0] = __expf(S[j][0] - nm0); ls0 += S[j][0];
            S[j][1] = __expf(S[j][1] - nm0); ls0 += S[j][1];
            S[j][2] = __expf(S[j][2] - nm1); ls1 += S[j][2];
            S[j][3] = __expf(S[j][3] - nm1); ls1 += S[j][3];
        }
        rs0 = rs0 * f0 + ls0;
        rs1 = rs1 * f1 + ls1;
        rm0 = nm0; rm1 = nm1;
        #pragma unroll
        for (int d = 0; d < 8; d++) {
            o[d][0] *= f0; o[d][1] *= f0; o[d][2] *= f1; o[d][3] *= f1;
        }

        u32 pa[4][4], pb[4][4];
        #pragma unroll
        for (int kp = 0; kp < 4; kp++) {
            bf16 h00,l00,h01,l01,h10,l10,h11,l11,h20,l20,h21,l21,h30,l30,h31,l31;
            split2(S[2*kp][0],h00,l00);   split2(S[2*kp][1],h01,l01);
            split2(S[2*kp][2],h10,l10);   split2(S[2*kp][3],h11,l11);
            split2(S[2*kp+1][0],h20,l20); split2(S[2*kp+1][1],h21,l21);
            split2(S[2*kp+1][2],h30,l30); split2(S[2*kp+1][3],h31,l31);
            pa[kp][0] = (u32)__bfloat16_as_ushort(h00) | ((u32)__bfloat16_as_ushort(h01) << 16);
            pa[kp][1] = (u32)__bfloat16_as_ushort(h10) | ((u32)__bfloat16_as_ushort(h11) << 16);
            pa[kp][2] = (u32)__bfloat16_as_ushort(h20) | ((u32)__bfloat16_as_ushort(h21) << 16);
            pa[kp][3] = (u32)__bfloat16_as_ushort(h30) | ((u32)__bfloat16_as_ushort(h31) << 16);
            pb[kp][0] = (u32)__bfloat16_as_ushort(l00) | ((u32)__bfloat16_as_ushort(l01) << 16);
            pb[kp][1] = (u32)__bfloat16_as_ushort(l10) | ((u32)__bfloat16_as_ushort(l11) << 16);
            pb[kp][2] = (u32)__bfloat16_as_ushort(l20) | ((u32)__bfloat16_as_ushort(l21) << 16);
            pb[kp][3] = (u32)__bfloat16_as_ushort(l30) | ((u32)__bfloat16_as_ushort(l31) << 16);
        }

        const u32 vbase = st + 2 * HKV;
        const u32 vrow  = (u32)((lane & 7) + 8 * ((lane >> 3) & 1));
        const u32 vcolb = (u32)((lane >> 4) * 16);
        #pragma unroll
        for (int kp = 0; kp < 4; kp++) {
            #pragma unroll
            for (int dp = 0; dp < 4; dp++) {
                u32 vd = vbase + (u32)((kp * 16 + vrow) * ROWB) + (u32)(dp * 32) + vcolb;
                u32 r0, r1, r2, r3;
                u32 vhf[2][2], vlf[2][2];
                LDSM4T(r0, r1, r2, r3, vd);
                vhf[0][0] = r0; vhf[0][1] = r1; vhf[1][0] = r2; vhf[1][1] = r3;
                LDSM4T(r0, r1, r2, r3, vd + HKV);
                vlf[0][0] = r0; vlf[0][1] = r1; vlf[1][0] = r2; vlf[1][1] = r3;
                #pragma unroll
                for (int u = 0; u < 2; u++) {
                    mma_bf16(o[2*dp+u], pa[kp], vhf[u]);
                    mma_bf16(o[2*dp+u], pb[kp], vhf[u]);
                    mma_bf16(o[2*dp+u], pa[kp], vlf[u]);
                }
            }
        }
    }

    rs0 += __shfl_xor_sync(0xffffffffu, rs0, 1);
    rs0 += __shfl_xor_sync(0xffffffffu, rs0, 2);
    rs1 += __shfl_xor_sync(0xffffffffu, rs1, 1);
    rs1 += __shfl_xor_sync(0xffffffffu, rs1, 2);
    const float i0 = 1.0f / rs0, i1 = 1.0f / rs1;
    const int row0 = q0 + wid * 16 + g4;
    #pragma unroll
    for (int d = 0; d < 8; d++) {
        const int col = h * 64 + d * 8 + t4 * 2;
        bf16 h0, l0, h1, l1;
        split2(o[d][0] * i0, h0, l0); split2(o[d][1] * i0, h1, l1);
        *(u32*)(oh + ((size_t)b * SQ + row0) * DM + col) =
            (u32)__bfloat16_as_ushort(h0) | ((u32)__bfloat16_as_ushort(h1) << 16);
        *(u32*)(ol + ((size_t)b * SQ + row0) * DM + col) =
            (u32)__bfloat16_as_ushort(l0) | ((u32)__bfloat16_as_ushort(l1) << 16);
        split2(o[d][2] * i1, h0, l0); split2(o[d][3] * i1, h1, l1);
        *(u32*)(oh + ((size_t)b * SQ + row0 + 8) * DM + col) =
            (u32)__bfloat16_as_ushort(h0) | ((u32)__bfloat16_as_ushort(h1) << 16);
        *(u32*)(ol + ((size_t)b * SQ + row0 + 8) * DM + col) =
            (u32)__bfloat16_as_ushort(l0) | ((u32)__bfloat16_as_ushort(l1) << 16);
    }
}

// ------------------- merged split fp32 -> (hi, lo) bf16 -------------------
struct SplitTab {
    const float* x[8];
    bf16* h[8];
    bf16* l[8];
    int endblk[8];
};

__global__ __launch_bounds__(256)
void splitall_k(SplitTab t)
{
    int bk = blockIdx.x;
    int r = 0;
    #pragma unroll
    for (int j = 0; j < 8; j++) if (bk >= t.endblk[j]) r = j + 1;
    int start = r ? t.endblk[r - 1] : 0;
    size_t i = (size_t)(bk - start) * 256 + threadIdx.x;
    float4 v = ((const float4*)t.x[r])[i];
    bf16 h0,l0,h1,l1,h2,l2,h3,l3;
    split2(v.x,h0,l0); split2(v.y,h1,l1); split2(v.z,h2,l2); split2(v.w,h3,l3);
    uint2 hp = make_uint2((u32)__bfloat16_as_ushort(h0) | ((u32)__bfloat16_as_ushort(h1)<<16),
                          (u32)__bfloat16_as_ushort(h2) | ((u32)__bfloat16_as_ushort(h3)<<16));
    uint2 lp = make_uint2((u32)__bfloat16_as_ushort(l0) | ((u32)__bfloat16_as_ushort(l1)<<16),
                          (u32)__bfloat16_as_ushort(l2) | ((u32)__bfloat16_as_ushort(l3)<<16));
    ((uint2*)t.h[r])[i] = hp;
    ((uint2*)t.l[r])[i] = lp;
}

// ------------------- LayerNorm rows of 1024 -------------------
template<int OUTM>
__global__ __launch_bounds__(256)
void ln_k(const float* __restrict__ x, float* __restrict__ y,
          bf16* __restrict__ yh, bf16* __restrict__ yl,
          const float* __restrict__ gg, const float* __restrict__ bb)
{
    const float* p = x + (size_t)blockIdx.x * DM;
    const int tid = threadIdx.x, lane = tid & 31, warp = tid >> 5;
    __shared__ float r1[8], r2[8];

    float4 v4 = ((const float4*)p)[tid];
    float v[4] = {v4.x, v4.y, v4.z, v4.w};
    float sm = v[0]+v[1]+v[2]+v[3];
    float s2 = v[0]*v[0]+v[1]*v[1]+v[2]*v[2]+v[3]*v[3];
    #pragma unroll
    for (int o = 16; o; o >>= 1) {
        sm += __shfl_xor_sync(0xffffffffu, sm, o);
        s2 += __shfl_xor_sync(0xffffffffu, s2, o);
    }
    if (!lane) { r1[warp] = sm; r2[warp] = s2; }
    __syncthreads();
    sm = 0.0f; s2 = 0.0f;
    #pragma unroll
    for (int i = 0; i < 8; i++) { sm += r1[i]; s2 += r2[i]; }
    const float mean = sm * (1.0f / DM);
    const float var  = s2 * (1.0f / DM) - mean * mean;
    const float inv  = rsqrtf(var + 1e-5f);

    float4 g4 = ((const float4*)gg)[tid];
    float4 b4 = ((const float4*)bb)[tid];
    float o0 = (v[0]-mean)*inv*g4.x + b4.x;
    float o1 = (v[1]-mean)*inv*g4.y + b4.y;
    float o2 = (v[2]-mean)*inv*g4.z + b4.z;
    float o3 = (v[3]-mean)*inv*g4.w + b4.w;
    if (OUTM == 0) {
        ((float4*)(y + (size_t)blockIdx.x * DM))[tid] = make_float4(o0,o1,o2,o3);
    } else {
        bf16 h0,l0,h1,l1,h2,l2,h3,l3;
        split2(o0,h0,l0); split2(o1,h1,l1); split2(o2,h2,l2); split2(o3,h3,l3);
        uint2 hp = make_uint2((u32)__bfloat16_as_ushort(h0) | ((u32)__bfloat16_as_ushort(h1)<<16),
                              (u32)__bfloat16_as_ushort(h2) | ((u32)__bfloat16_as_ushort(h3)<<16));
        uint2 lp = make_uint2((u32)__bfloat16_as_ushort(l0) | ((u32)__bfloat16_as_ushort(l1)<<16),
                              (u32)__bfloat16_as_ushort(l2) | ((u32)__bfloat16_as_ushort(l3)<<16));
        ((uint2*)(yh + (size_t)blockIdx.x * DM))[tid] = hp;
        ((uint2*)(yl + (size_t)blockIdx.x * DM))[tid] = lp;
    }
}

// ------------------- launch -------------------
#define SMEM_GEMM (2 * 4 * 128 * 80)    // 81920
#define SMEM_FLASH (2 * 4 * 64 * 144)   // 73728

extern "C" void kernel_launch(void* const* d_in, const int* in_sizes, int n_in,
                              void* d_out, int out_size)
{
    const float* x_q  = (const float*)d_in[0];
    const float* x_kv = (const float*)d_in[1];
    const float* bias = (const float*)d_in[2];
    const float* Wq   = (const float*)d_in[3];
    const float* Wk   = (const float*)d_in[4];
    const float* Wv   = (const float*)d_in[5];
    const float* Wo   = (const float*)d_in[6];
    const float* W1   = (const float*)d_in[7];
    const float* b1   = (const float*)d_in[8];
    const float* W2   = (const float*)d_in[9];
    const float* b2   = (const float*)d_in[10];
    const float* g1   = (const float*)d_in[11];
    const float* be1  = (const float*)d_in[12];
    const float* g2   = (const float*)d_in[13];
    const float* be2  = (const float*)d_in[14];
    float* out = (float*)d_out;

    bf16 *xqh,*xql,*xkh,*xkl,*wqh,*wql,*wkh,*wkl,*wvh,*wvl,*woh,*wol,*w1h,*w1l,*w2h,*w2l;
    bf16 *qh,*ql,*kh,*kl,*vh,*vl,*oh,*ol,*lnh,*lnl,*hH,*hL;
    float *x1,*x2;
    cudaGetSymbolAddress((void**)&xqh, s_xq_h); cudaGetSymbolAddress((void**)&xql, s_xq_l);
    cudaGetSymbolAddress((void**)&xkh, s_xk_h); cudaGetSymbolAddress((void**)&xkl, s_xk_l);
    cudaGetSymbolAddress((void**)&wqh, s_wq_h); cudaGetSymbolAddress((void**)&wql, s_wq_l);
    cudaGetSymbolAddress((void**)&wkh, s_wk_h); cudaGetSymbolAddress((void**)&wkl, s_wk_l);
    cudaGetSymbolAddress((void**)&wvh, s_wv_h); cudaGetSymbolAddress((void**)&wvl, s_wv_l);
    cudaGetSymbolAddress((void**)&woh, s_wo_h); cudaGetSymbolAddress((void**)&wol, s_wo_l);
    cudaGetSymbolAddress((void**)&w1h, s_w1_h); cudaGetSymbolAddress((void**)&w1l, s_w1_l);
    cudaGetSymbolAddress((void**)&w2h, s_w2_h); cudaGetSymbolAddress((void**)&w2l, s_w2_l);
    cudaGetSymbolAddress((void**)&qh,  s_q_h);  cudaGetSymbolAddress((void**)&ql,  s_q_l);
    cudaGetSymbolAddress((void**)&kh,  s_k_h);  cudaGetSymbolAddress((void**)&kl,  s_k_l);
    cudaGetSymbolAddress((void**)&vh,  s_v_h);  cudaGetSymbolAddress((void**)&vl,  s_v_l);
    cudaGetSymbolAddress((void**)&oh,  s_o_h);  cudaGetSymbolAddress((void**)&ol,  s_o_l);
    cudaGetSymbolAddress((void**)&x1,  s_x1);
    cudaGetSymbolAddress((void**)&lnh, s_ln_h); cudaGetSymbolAddress((void**)&lnl, s_ln_l);
    cudaGetSymbolAddress((void**)&hH,  s_hh);   cudaGetSymbolAddress((void**)&hL,  s_hl);
    cudaGetSymbolAddress((void**)&x2,  s_x2);

    cudaFuncSetAttribute(gemm_mma<0,1>, cudaFuncAttributeMaxDynamicSharedMemorySize, SMEM_GEMM);
    cudaFuncSetAttribute(gemm_mma<1,0>, cudaFuncAttributeMaxDynamicSharedMemorySize, SMEM_GEMM);
    cudaFuncSetAttribute(gemm_mma<2,1>, cudaFuncAttributeMaxDynamicSharedMemorySize, SMEM_GEMM);
    cudaFuncSetAttribute(gemm_mma<3,0>, cudaFuncAttributeMaxDynamicSharedMemorySize, SMEM_GEMM);
    cudaFuncSetAttribute(flash_k,       cudaFuncAttributeMaxDynamicSharedMemorySize, SMEM_FLASH);

    // one merged split launch for all 8 fp32->bf16 hi/lo conversions
    {
        SplitTab t;
        t.x[0]=x_q;  t.h[0]=xqh; t.l[0]=xql;
        t.x[1]=x_kv; t.h[1]=xkh; t.l[1]=xkl;
        t.x[2]=Wq;   t.h[2]=wqh; t.l[2]=wql;
        t.x[3]=Wk;   t.h[3]=wkh; t.l[3]=wkl;
        t.x[4]=Wv;   t.h[4]=wvh; t.l[4]=wvl;
        t.x[5]=Wo;   t.h[5]=woh; t.l[5]=wol;
        t.x[6]=W1;   t.h[6]=w1h; t.l[6]=w1l;
        t.x[7]=W2;   t.h[7]=w2h; t.l[7]=w2l;
        int blks[8] = {MR*DM/1024, MR*DM/1024, DM*DM/1024, DM*DM/1024,
                       DM*DM/1024, DM*DM/1024, FF*DM/1024, DM*FF/1024};
        int acc_ = 0;
        for (int j = 0; j < 8; j++) { acc_ += blks[j]; t.endblk[j] = acc_; }
        splitall_k<<<acc_, 256>>>(t);
    }

    // Q, K, V projections (all split out)
    {
        dim3 gr(DM/128, MR/128, 1);
        gemm_mma<0,1><<<gr, 128, SMEM_GEMM>>>(xqh, xql, wqh, wql, nullptr, qh, ql,
            DM, DM, DM, DM, 0, 0, 0, 1.0f, nullptr, 0, 0, nullptr);
        gemm_mma<0,1><<<gr, 128, SMEM_GEMM>>>(xkh, xkl, wkh, wkl, nullptr, kh, kl,
            DM, DM, DM, DM, 0, 0, 0, 1.0f, nullptr, 0, 0, nullptr);
        gemm_mma<0,1><<<gr, 128, SMEM_GEMM>>>(xkh, xkl, wvh, wvl, nullptr, vh, vl,
            DM, DM, DM, DM, 0, 0, 0, 1.0f, nullptr, 0, 0, nullptr);
    }

    // fused attention
    flash_k<<<dim3(SQ/128, NHD, BB), 256, SMEM_FLASH>>>(qh, ql, kh, kl, vh, vl, bias, oh, ol);

    // x1 = x_q + O @ Wo^T
    gemm_mma<1,0><<<dim3(DM/128, MR/128, 1), 128, SMEM_GEMM>>>(
        oh, ol, woh, wol, x1, nullptr, nullptr,
        DM, DM, DM, DM, 0, 0, 0, 1.0f, x_q, DM, 0, nullptr);

    ln_k<1><<<MR, 256>>>(x1, nullptr, lnh, lnl, g1, be1);

    // h = gelu(ln1 @ W1^T + b1)  (split out)
    gemm_mma<2,1><<<dim3(FF/128, MR/128, 1), 128, SMEM_GEMM>>>(
        lnh, lnl, w1h, w1l, nullptr, hH, hL,
        DM, DM, DM, FF, 0, 0, 0, 1.0f, nullptr, 0, 0, b1);

    // x2 = x1 + h @ W2^T + b2
    gemm_mma<3,0><<<dim3(DM/128, MR/128, 1), 128, SMEM_GEMM>>>(
        hH, hL, w2h, w2l, x2, nullptr, nullptr,
        FF, FF, FF, DM, 0, 0, 0, 1.0f, x1, DM, 0, b2);

    ln_k<0><<<MR, 256>>>(x2, out, nullptr, nullptr, g2, be2);
}